// round 15
// baseline (speedup 1.0000x reference)
#include <cuda_runtime.h>
#include <cuda_fp16.h>
#include <cuda.h>
#include <math.h>
#include <stdint.h>

#define D_MODEL     2048
#define NUM_CLASSES 50257
#define NB          2048
#define HIDDEN      128
#define NBASIS      8
#define RANK        4
#define KP2         2112      // padded K: 33 * 64
#define NPAD2       50688     // padded N: 99 * 512
#define CHUNKS      264       // KP2 / 8
#define LN_EPS      1e-5f

// ---- tcgen05 persistent config: M256 x N512 cluster tile, 74 clusters ----
#define GBN         512
#define GBK         64
#define KTILES      33
#define NTILES      (8 * (NPAD2 / GBN))   // 792
#define NCLUSTERS   74
#define GSTAGES     3
#define STAGE_BYTES 49152     // A 16KB + B0 16KB + B1 16KB
#define OFF_TMEM    0
#define OFF_FULL    8
#define OFF_EMPTY   40
#define OFF_DONE    72        // epi_done (leader, count=2)
#define OFF_EPIF    80        // epi_full (per CTA, count=1)
#define OFF_TILE    1024
#define OFF_EPI     (OFF_TILE + GSTAGES * STAGE_BYTES)   // 148480
#define SMEM_TOTAL  (OFF_EPI + 8 * 4608)                 // 185344
#define IDESC       0x10400010u

// ---- prep kernel block roles: one block per row, NO divisions ----
#define PREP_CTX    128
#define PREP_CX     NB                    // 2048 conv_x blocks (1 row each)
#define PREP_CW     NPAD2                 // 50688 conv_w blocks (1 row each)
#define PREP_GRID   (PREP_CTX + PREP_CX + PREP_CW)
#define PREP_SMEM   27584

// ---- HMMA fallback tile config ----
#define FBM         128
#define FBK         32
#define FKT         66
#define FSTAGES     4
#define FPITCH      40
#define FSTB        (FBM * FPITCH * 2)

#if defined(__CUDA_ARCH_FEAT_SM103_ALL) || (__CUDA_ARCH_SPECIFIC__ == 1030)
#define HAS_TCGEN05 1
#else
#define HAS_TCGEN05 0
#endif

__device__ __half g_Ah[(size_t)NB * KP2];
__device__ __half g_Bh[(size_t)NPAD2 * KP2];

union H8 { __half h[8]; uint4 u; };

__device__ __forceinline__ void cvt8(H8& o, const float* p) {
    float4 v0 = *(const float4*)p;
    float4 v1 = *(const float4*)(p + 4);
    o.h[0]=__float2half_rn(v0.x); o.h[1]=__float2half_rn(v0.y);
    o.h[2]=__float2half_rn(v0.z); o.h[3]=__float2half_rn(v0.w);
    o.h[4]=__float2half_rn(v1.x); o.h[5]=__float2half_rn(v1.y);
    o.h[6]=__float2half_rn(v1.z); o.h[7]=__float2half_rn(v1.w);
}

// ============================================================================
// prep kernel: one block per row for conv roles (zero integer division)
// ============================================================================
__global__ __launch_bounds__(256) void prep(
        const float* __restrict__ ctx, const float* __restrict__ cw,
        const float* __restrict__ cb,  const float* __restrict__ lg,
        const float* __restrict__ lb,  const float* __restrict__ cfw,
        const float* __restrict__ cfb, const float* __restrict__ x,
        const float* __restrict__ A,
        const float* __restrict__ w,   const float* __restrict__ bB) {
    __shared__ char buf[PREP_SMEM];
    const int tid = threadIdx.x;
    const int bb = blockIdx.x;

    if (bb >= PREP_CTX + PREP_CX) {
        // ---- conv_w: one row per block; thread tid = chunk tid ----
        const int row = bb - PREP_CTX - PREP_CX;
        __half* dst = g_Bh + (size_t)row * KP2;
        H8 o;
        if (row < NUM_CLASSES) {
            cvt8(o, w + (size_t)row * D_MODEL + tid * 8);
        } else {
            #pragma unroll
            for (int i = 0; i < 8; i++) o.h[i] = __float2half_rn(0.f);
        }
        *(uint4*)(dst + tid * 8) = o.u;
        if (tid < 8) {          // tail chunks 256..263
            H8 t;
            if (row < NUM_CLASSES && tid < 4) {
                int nn = tid * 2;
                float4 a = *(const float4*)(bB + ((size_t)nn       * NUM_CLASSES + row) * 4);
                float4 b = *(const float4*)(bB + ((size_t)(nn + 1) * NUM_CLASSES + row) * 4);
                t.h[0]=__float2half_rn(a.x); t.h[1]=__float2half_rn(a.y);
                t.h[2]=__float2half_rn(a.z); t.h[3]=__float2half_rn(a.w);
                t.h[4]=__float2half_rn(b.x); t.h[5]=__float2half_rn(b.y);
                t.h[6]=__float2half_rn(b.z); t.h[7]=__float2half_rn(b.w);
            } else {
                #pragma unroll
                for (int i = 0; i < 8; i++) t.h[i] = __float2half_rn(0.f);
            }
            *(uint4*)(dst + (256 + tid) * 8) = t.u;
        }
        return;
    }

    if (bb >= PREP_CTX) {
        // ---- conv_x: one row per block ----
        const int row = bb - PREP_CTX;
        __half* dst = g_Ah + (size_t)row * KP2;
        H8 o;
        cvt8(o, x + (size_t)row * D_MODEL + tid * 8);
        *(uint4*)(dst + tid * 8) = o.u;
        if (tid < 8) {          // pad chunks 256..263 (u-lane 2080..2111 zero; 2048..2079 overwritten by lora later)
            H8 t;
            #pragma unroll
            for (int i = 0; i < 8; i++) t.h[i] = __float2half_rn(0.f);
            *(uint4*)(dst + (256 + tid) * 8) = t.u;
        }
        return;
    }

    // ---- fused ctx chain ----
    float* Ws  = (float*)buf;
    float* Xs  = (float*)(buf + 16384);
    float* As  = (float*)buf;
    float* Xs2 = (float*)(buf + 16512);
    float* cfs = (float*)(buf + 24960);
    float* ys  = (float*)(buf + 25472);

    const int tn = tid & 31;
    const int tm = tid >> 5;
    const int b0 = bb * 16;

    float acc[2][4];
    #pragma unroll
    for (int i = 0; i < 2; i++)
        #pragma unroll
        for (int j = 0; j < 4; j++) acc[i][j] = 0.f;

    for (int k0 = 0; k0 < D_MODEL; k0 += 32) {
        if (tid < 128) {
            int row = tid >> 3, c4 = tid & 7;
            *(float4*)&Xs[row * 36 + c4 * 4] =
                *(const float4*)(ctx + (size_t)(b0 + row) * D_MODEL + k0 + c4 * 4);
        }
        #pragma unroll
        for (int i = 0; i < 4; i++) {
            int idx = tid + i * 256;
            int j = idx >> 3, c4 = idx & 7;
            float4 v = *(const float4*)(cw + (size_t)j * D_MODEL + k0 + c4 * 4);
            Ws[(c4*4+0)*128 + j] = v.x;
            Ws[(c4*4+1)*128 + j] = v.y;
            Ws[(c4*4+2)*128 + j] = v.z;
            Ws[(c4*4+3)*128 + j] = v.w;
        }
        __syncthreads();
        #pragma unroll 8
        for (int kk = 0; kk < 32; kk++) {
            float x0 = Xs[(tm*2)*36 + kk], x1 = Xs[(tm*2+1)*36 + kk];
            float4 wv = *(const float4*)&Ws[kk*128 + tn*4];
            acc[0][0] += x0*wv.x; acc[0][1] += x0*wv.y;
            acc[0][2] += x0*wv.z; acc[0][3] += x0*wv.w;
            acc[1][0] += x1*wv.x; acc[1][1] += x1*wv.y;
            acc[1][2] += x1*wv.z; acc[1][3] += x1*wv.w;
        }
        __syncthreads();
    }
    {
        float4 cbv = *(const float4*)(cb + tn * 4);
        #pragma unroll
        for (int mi = 0; mi < 2; mi++) {
            acc[mi][0] += cbv.x; acc[mi][1] += cbv.y;
            acc[mi][2] += cbv.z; acc[mi][3] += cbv.w;
        }
    }

    float4 lgv = *(const float4*)(lg + tn * 4);
    float4 lbv = *(const float4*)(lb + tn * 4);
    #pragma unroll
    for (int mi = 0; mi < 2; mi++) {
        float s = acc[mi][0]+acc[mi][1]+acc[mi][2]+acc[mi][3];
        float s2 = acc[mi][0]*acc[mi][0]+acc[mi][1]*acc[mi][1]
                 + acc[mi][2]*acc[mi][2]+acc[mi][3]*acc[mi][3];
        #pragma unroll
        for (int o = 16; o > 0; o >>= 1) {
            s  += __shfl_xor_sync(0xffffffffu, s,  o);
            s2 += __shfl_xor_sync(0xffffffffu, s2, o);
        }
        float mu = s * (1.f/128.f);
        float var = s2 * (1.f/128.f) - mu*mu;
        float rstd = rsqrtf(var + LN_EPS);
        float g[4];
        const float* lgp = (const float*)&lgv;
        const float* lbp = (const float*)&lbv;
        #pragma unroll
        for (int ni = 0; ni < 4; ni++) {
            float hn = (acc[mi][ni] - mu) * rstd * lgp[ni] + lbp[ni];
            g[ni] = 0.5f * hn * (1.f + erff(hn * 0.70710678118654752f));
        }
        #pragma unroll
        for (int n = 0; n < NBASIS; n++) {
            float4 wv = *(const float4*)(cfw + n * HIDDEN + tn * 4);
            float p = g[0]*wv.x + g[1]*wv.y + g[2]*wv.z + g[3]*wv.w;
            #pragma unroll
            for (int o = 16; o > 0; o >>= 1) p += __shfl_xor_sync(0xffffffffu, p, o);
            if (tn == 0) cfs[(tm*2+mi)*8 + n] = p + cfb[n];
        }
    }
    __syncthreads();

    float y0 = 0.f, y1 = 0.f;
    for (int k0 = 0; k0 < D_MODEL; k0 += 128) {
        #pragma unroll
        for (int i = 0; i < 4; i++) {
            int idx = tid + i * 256;
            int j = idx >> 5, c4 = idx & 31;
            float4 v = *(const float4*)(A + (size_t)j * D_MODEL + k0 + c4 * 4);
            float* dst = &As[j * 129 + c4 * 4];
            dst[0] = v.x; dst[1] = v.y; dst[2] = v.z; dst[3] = v.w;
        }
        #pragma unroll
        for (int i = 0; i < 2; i++) {
            int idx = tid + i * 256;
            int r = idx >> 5, c4 = idx & 31;
            *(float4*)&Xs2[r * 132 + c4 * 4] =
                *(const float4*)(x + (size_t)(b0 + r) * D_MODEL + k0 + c4 * 4);
        }
        __syncthreads();
        const float* ar = As + tn * 129;
        const float* x0p = Xs2 + (tm*2) * 132;
        const float* x1p = Xs2 + (tm*2+1) * 132;
        #pragma unroll 16
        for (int kk = 0; kk < 128; kk++) {
            float a = ar[kk];
            y0 += a * x0p[kk];
            y1 += a * x1p[kk];
        }
        __syncthreads();
    }
    ys[(tm*2)*33 + tn]   = y0;
    ys[(tm*2+1)*33 + tn] = y1;
    __syncthreads();

    if (tid < 64) {
        int row = tid >> 2, r = tid & 3;
        float cfr[8], z = 0.f;
        #pragma unroll
        for (int n = 0; n < 8; n++) {
            cfr[n] = cfs[row*8 + n];
            z += cfr[n] * ys[row*33 + n*4 + r];
        }
        #pragma unroll
        for (int n = 0; n < 8; n++)
            g_Ah[(size_t)(b0 + row) * KP2 + D_MODEL + n*4 + r] = __float2half_rn(cfr[n] * z);
    }
}

// ============================================================================
// helpers
// ============================================================================
__device__ __forceinline__ uint32_t smem_u32(const void* p) {
    return (uint32_t)__cvta_generic_to_shared(p);
}
__device__ __forceinline__ void mbar_init(uint32_t a, uint32_t cnt) {
    asm volatile("mbarrier.init.shared.b64 [%0], %1;" :: "r"(a), "r"(cnt) : "memory");
}
__device__ __forceinline__ void mbar_expect_tx(uint32_t a, uint32_t bytes) {
    asm volatile("mbarrier.arrive.expect_tx.shared.b64 _, [%0], %1;" :: "r"(a), "r"(bytes) : "memory");
}
__device__ __forceinline__ void mbar_wait(uint32_t a, uint32_t parity) {
    asm volatile(
        "{\n\t.reg .pred P1;\n\t"
        "WL_%=:\n\t"
        "mbarrier.try_wait.parity.acquire.cta.shared::cta.b64 P1, [%0], %1, 0x989680;\n\t"
        "@P1 bra.uni WD_%=;\n\t"
        "bra.uni WL_%=;\n\t"
        "WD_%=:\n\t}" :: "r"(a), "r"(parity) : "memory");
}
__device__ __forceinline__ void mbar_wait_relaxed(uint32_t a, uint32_t parity) {
    asm volatile(
        "{\n\t.reg .pred P1;\n\t"
        "WL_%=:\n\t"
        "mbarrier.try_wait.parity.relaxed.cta.shared::cta.b64 P1, [%0], %1, 0x989680;\n\t"
        "@P1 bra.uni WD_%=;\n\t"
        "bra.uni WL_%=;\n\t"
        "WD_%=:\n\t}" :: "r"(a), "r"(parity) : "memory");
}
__device__ __forceinline__ uint32_t elect_one() {
    uint32_t pred;
    asm volatile("{\n\t.reg .pred p;\n\telect.sync _|p, 0xFFFFFFFF;\n\t"
                 "selp.b32 %0, 1, 0, p;\n\t}" : "=r"(pred));
    return pred;
}
__device__ __forceinline__ uint32_t ctarank() {
    uint32_t r; asm("mov.u32 %0, %%cluster_ctarank;" : "=r"(r)); return r;
}
__device__ __forceinline__ void mbar_arrive_leader(uint32_t a) {
    asm volatile(
        "{\n\t.reg .b32 la;\n\tand.b32 la, %0, 0xFEFFFFFF;\n\t"
        "mbarrier.arrive.shared::cluster.b64 _, [la];\n\t}"
        :: "r"(a) : "memory");
}

#define CP16(d, s)  asm volatile("cp.async.cg.shared.global [%0], [%1], 16;" :: "r"(d), "l"(s))
#define CP_COMMIT() asm volatile("cp.async.commit_group;")
#define CP_WAIT(n)  asm volatile("cp.async.wait_group %0;" :: "n"(n))
__device__ __forceinline__ void ldsm4(uint32_t& r0, uint32_t& r1, uint32_t& r2, uint32_t& r3, uint32_t a) {
    asm volatile("ldmatrix.sync.aligned.m8n8.x4.shared.b16 {%0,%1,%2,%3}, [%4];"
                 : "=r"(r0), "=r"(r1), "=r"(r2), "=r"(r3) : "r"(a));
}
__device__ __forceinline__ void mma16816(float* c, const uint32_t* a, const uint32_t* b) {
    asm volatile("mma.sync.aligned.m16n8k16.row.col.f32.f16.f16.f32 "
                 "{%0,%1,%2,%3}, {%4,%5,%6,%7}, {%8,%9}, {%0,%1,%2,%3};"
                 : "+f"(c[0]), "+f"(c[1]), "+f"(c[2]), "+f"(c[3])
                 : "r"(a[0]), "r"(a[1]), "r"(a[2]), "r"(a[3]), "r"(b[0]), "r"(b[1]));
}

// ============================================================================
// persistent main GEMM: 74 clusters, M256xN512 tiles, 320 threads
// warps 0-7 epilogue (pitch-36 STS.128 staging), warp 8 producer,
// warp 9 consumer (+TMEM alloc)
// ============================================================================
__global__ void __launch_bounds__(320, 1) __cluster_dims__(2, 1, 1)
gemm_tc(const __grid_constant__ CUtensorMap tmA,
        const __grid_constant__ CUtensorMap tmB,
        const float* __restrict__ bias,
        float* __restrict__ out) {
    extern __shared__ char smem[];
#if HAS_TCGEN05
    const uint32_t sb = smem_u32(smem);
    const int tid = threadIdx.x;
    const int wid = tid >> 5;
    const int lane = tid & 31;
    const uint32_t rank = ctarank();
    const int cid = blockIdx.x >> 1;

    if (tid == 0) {
        #pragma unroll
        for (int s = 0; s < GSTAGES; s++) {
            mbar_init(sb + OFF_FULL  + s * 8, 1);
            mbar_init(sb + OFF_EMPTY + s * 8, 1);
        }
        mbar_init(sb + OFF_DONE, 2);
        mbar_init(sb + OFF_EPIF, 1);
    }
    if (wid == 9) {
        asm volatile("tcgen05.alloc.cta_group::2.sync.aligned.shared::cta.b32 [%0], %1;"
                     :: "r"(sb + OFF_TMEM), "r"(512u) : "memory");
    }
    __syncthreads();
    uint32_t tbase;
    asm volatile("ld.shared.b32 %0, [%1];" : "=r"(tbase) : "r"(sb + OFF_TMEM));

    asm volatile("barrier.cluster.arrive.aligned;" ::: "memory");
    asm volatile("barrier.cluster.wait.aligned;" ::: "memory");

    // ---- producer: warp 8 lane 0 in BOTH CTAs, continuous stage ring ----
    if (tid == 256) {
        int pphase = 1, pstage = 0;
        for (int t = cid; t < NTILES; t += NCLUSTERS) {
            const int arow = (t & 7) * 256 + (int)rank * 128;
            const int n0   = (t >> 3) * GBN;
            for (int kt = 0; kt < KTILES; kt++) {
                mbar_wait_relaxed(sb + OFF_EMPTY + pstage * 8, (uint32_t)pphase);
                if (rank == 0) mbar_expect_tx(sb + OFF_FULL + pstage * 8, 2 * STAGE_BYTES);
                const int k0 = kt * GBK;
                const uint32_t st = sb + OFF_TILE + pstage * STAGE_BYTES;
                const uint32_t fb = sb + OFF_FULL + pstage * 8;
                asm volatile(
                    "{\n\t.reg .b32 lb;\n\tand.b32 lb, %5, 0xFEFFFFFF;\n\t"
                    "cp.async.bulk.tensor.3d.cta_group::2.shared::cluster.global"
                    ".tile.mbarrier::complete_tx::bytes [%0], [%1, {%2, %3, %4}], [lb];\n\t}"
                    :: "r"(st), "l"(&tmA), "r"(k0), "r"(arow), "r"(0), "r"(fb) : "memory");
                asm volatile(
                    "{\n\t.reg .b32 lb;\n\tand.b32 lb, %5, 0xFEFFFFFF;\n\t"
                    "cp.async.bulk.tensor.3d.cta_group::2.shared::cluster.global"
                    ".tile.mbarrier::complete_tx::bytes [%0], [%1, {%2, %3, %4}], [lb];\n\t}"
                    :: "r"(st + 16384), "l"(&tmB), "r"(k0), "r"(n0 + (int)rank * 128), "r"(0), "r"(fb) : "memory");
                asm volatile(
                    "{\n\t.reg .b32 lb;\n\tand.b32 lb, %5, 0xFEFFFFFF;\n\t"
                    "cp.async.bulk.tensor.3d.cta_group::2.shared::cluster.global"
                    ".tile.mbarrier::complete_tx::bytes [%0], [%1, {%2, %3, %4}], [lb];\n\t}"
                    :: "r"(st + 32768), "l"(&tmB), "r"(k0), "r"(n0 + 256 + (int)rank * 128), "r"(0), "r"(fb) : "memory");
                if (++pstage == GSTAGES) { pstage = 0; pphase ^= 1; }
            }
        }
    }

    // ---- consumer: warp 9, leader CTA, one elected thread ----
    if (wid == 9 && rank == 0) {
        if (elect_one()) {
            int cphase = 0, cstage = 0, ti = 0;
            for (int t = cid; t < NTILES; t += NCLUSTERS, ti++) {
                if (ti > 0) {
                    mbar_wait(sb + OFF_DONE, (uint32_t)((ti - 1) & 1));
                    asm volatile("tcgen05.fence::after_thread_sync;" ::: "memory");
                }
                for (int kt = 0; kt < KTILES; kt++) {
                    mbar_wait(sb + OFF_FULL + cstage * 8, (uint32_t)cphase);
                    const uint32_t st = sb + OFF_TILE + cstage * STAGE_BYTES;
                    const uint64_t dbase = (uint64_t(2) << 61) | (uint64_t(1) << 46)
                                         | (uint64_t(64) << 32) | (uint64_t(1) << 16);
                    const uint64_t ad  = dbase | ((uint64_t)(st >> 4) & 0x3FFF);
                    const uint64_t bd0 = dbase | ((uint64_t)((st + 16384) >> 4) & 0x3FFF);
                    const uint64_t bd1 = dbase | ((uint64_t)((st + 32768) >> 4) & 0x3FFF);
                    #pragma unroll
                    for (int ks = 0; ks < 4; ks++) {
                        uint32_t en = (kt | ks) ? 1u : 0u;
                        asm volatile(
                            "{\n\t.reg .pred p;\n\tsetp.ne.u32 p, %5, 0;\n\t"
                            "tcgen05.mma.cta_group::2.kind::f16 [%0], %1, %2, %3, "
                            "{%4,%4,%4,%4,%4,%4,%4,%4}, p;\n\t}"
                            :: "r"(tbase), "l"(ad + ks*2), "l"(bd0 + ks*2), "r"(IDESC), "r"(0u), "r"(en) : "memory");
                        asm volatile(
                            "{\n\t.reg .pred p;\n\tsetp.ne.u32 p, %5, 0;\n\t"
                            "tcgen05.mma.cta_group::2.kind::f16 [%0], %1, %2, %3, "
                            "{%4,%4,%4,%4,%4,%4,%4,%4}, p;\n\t}"
                            :: "r"(tbase + 256), "l"(ad + ks*2), "l"(bd1 + ks*2), "r"(IDESC), "r"(0u), "r"(en) : "memory");
                    }
                    asm volatile(
                        "tcgen05.commit.cta_group::2.mbarrier::arrive::one.shared::cluster"
                        ".multicast::cluster.b64 [%0], %1;"
                        :: "r"(sb + OFF_EMPTY + cstage * 8), "h"((uint16_t)3) : "memory");
                    if (++cstage == GSTAGES) { cstage = 0; cphase ^= 1; }
                }
                asm volatile(
                    "tcgen05.commit.cta_group::2.mbarrier::arrive::one.shared::cluster"
                    ".multicast::cluster.b64 [%0], %1;"
                    :: "r"(sb + OFF_EPIF), "h"((uint16_t)3) : "memory");
            }
        }
    }

    // ---- epilogue: warps 0..7, both CTAs; pitch-36 STS.128 staging ----
    if (wid < 8) {
        const int sub  = wid & 3;       // TMEM subpartition (warp % 4)
        const int half = wid >> 2;      // column half of the 512
        float* tsm = (float*)(smem + OFF_EPI + wid * 4608);   // 32 x 36 fp32
        int ti = 0;
        for (int t = cid; t < NTILES; t += NCLUSTERS, ti++) {
            mbar_wait(sb + OFF_EPIF, (uint32_t)(ti & 1));
            asm volatile("tcgen05.fence::after_thread_sync;" ::: "memory");
            const int rowbase = (t & 7) * 256 + (int)rank * 128 + sub * 32;
            const int n0 = (t >> 3) * GBN;
            #pragma unroll 1
            for (int i = 0; i < 8; i++) {
                const int blk = half * 8 + i;
                const int cbase = n0 + blk * 32;
                if (cbase < NUM_CLASSES) {
                    uint32_t r[32];
                    asm volatile(
                        "tcgen05.ld.sync.aligned.32x32b.x32.b32 "
                        "{%0,%1,%2,%3,%4,%5,%6,%7,%8,%9,%10,%11,%12,%13,%14,%15,"
                        "%16,%17,%18,%19,%20,%21,%22,%23,%24,%25,%26,%27,%28,%29,%30,%31}, [%32];"
                        : "=r"(r[0]),"=r"(r[1]),"=r"(r[2]),"=r"(r[3]),"=r"(r[4]),"=r"(r[5]),
                          "=r"(r[6]),"=r"(r[7]),"=r"(r[8]),"=r"(r[9]),"=r"(r[10]),"=r"(r[11]),
                          "=r"(r[12]),"=r"(r[13]),"=r"(r[14]),"=r"(r[15]),"=r"(r[16]),"=r"(r[17]),
                          "=r"(r[18]),"=r"(r[19]),"=r"(r[20]),"=r"(r[21]),"=r"(r[22]),"=r"(r[23]),
                          "=r"(r[24]),"=r"(r[25]),"=r"(r[26]),"=r"(r[27]),"=r"(r[28]),"=r"(r[29]),
                          "=r"(r[30]),"=r"(r[31])
                        : "r"(tbase + blk * 32));
                    asm volatile("tcgen05.wait::ld.sync.aligned;" ::: "memory");
                    // STS.128 x8, pitch 36 floats (16B-aligned, conflict-free)
                    #pragma unroll
                    for (int q = 0; q < 8; q++) {
                        float4 v = make_float4(__uint_as_float(r[4*q]),   __uint_as_float(r[4*q+1]),
                                               __uint_as_float(r[4*q+2]), __uint_as_float(r[4*q+3]));
                        *(float4*)&tsm[lane * 36 + 4*q] = v;
                    }
                    __syncwarp();
                    const int c = cbase + lane;
                    const bool ok = (c < NUM_CLASSES);
                    const float bv = ok ? __ldg(bias + c) : 0.f;
                    #pragma unroll 8
                    for (int rr = 0; rr < 32; rr++) {
                        float v = tsm[rr * 36 + lane] + bv;
                        if (ok) out[(size_t)(rowbase + rr) * NUM_CLASSES + c] = v;
                    }
                    __syncwarp();
                }
            }
            asm volatile("bar.sync 3, 256;" ::: "memory");
            if (tid == 0) mbar_arrive_leader(sb + OFF_DONE);
        }
    }

    __syncthreads();
    if (wid == 9) {
        asm volatile("tcgen05.relinquish_alloc_permit.cta_group::2.sync.aligned;");
        asm volatile("tcgen05.dealloc.cta_group::2.sync.aligned.b32 %0, %1;"
                     :: "r"(tbase), "r"(512u));
    }
    asm volatile("barrier.cluster.arrive.aligned;" ::: "memory");
    asm volatile("barrier.cluster.wait.aligned;" ::: "memory");

#else  // ================= mma.sync fallback (base sm_103 cubin) =============
    const int tid  = threadIdx.x;
    const int lane = tid & 31;
    const int wid  = tid >> 5;
    if (wid < 8) {
        const int wm   = wid & 3;
        const int wn   = wid >> 2;

        __half* As = (__half*)smem;
        __half* Bs = (__half*)smem + (size_t)FSTAGES * FBM * FPITCH;
        const uint32_t sA = smem_u32(As), sB = smem_u32(Bs);

        const int crow = tid >> 2, cch = tid & 3;
        const uint32_t dA = sA + (crow * FPITCH + cch * 8) * 2;
        const uint32_t dB = sB + (crow * FPITCH + cch * 8) * 2;

        const int aRow = wm*32 + (lane & 15);
        const int aCol = (lane >> 4) << 3;
        const int bRow = wn*64 + (lane & 7) + ((lane >> 4) << 3);
        const int bCol = ((lane >> 3) & 1) << 3;
        const uint32_t aBase = sA + (aRow * FPITCH + aCol) * 2;
        const uint32_t bBase = sB + (bRow * FPITCH + bCol) * 2;

        const int FT = 16 * (NPAD2 / 128);
        for (int t = blockIdx.x; t < FT; t += gridDim.x) {
            const int m0 = (t & 15) * FBM;
            const int n0 = (t >> 4) * 128;
            const __half* gA = g_Ah + (size_t)(m0 + crow) * KP2 + cch * 8;
            const __half* gB = g_Bh + (size_t)(n0 + crow) * KP2 + cch * 8;

            float acc[2][8][4];
            #pragma unroll
            for (int i = 0; i < 2; i++)
                #pragma unroll
                for (int j = 0; j < 8; j++)
                    #pragma unroll
                    for (int k = 0; k < 4; k++) acc[i][j][k] = 0.f;

            #pragma unroll
            for (int s = 0; s < FSTAGES - 1; s++) {
                int koff = s * FBK;
                CP16(dA + s*FSTB,                 gA + koff);
                CP16(dA + s*FSTB + 64*FPITCH*2,   gA + (size_t)64*KP2 + koff);
                CP16(dB + s*FSTB,                 gB + koff);
                CP16(dB + s*FSTB + 64*FPITCH*2,   gB + (size_t)64*KP2 + koff);
                CP_COMMIT();
            }

            #pragma unroll 1
            for (int kt = 0; kt < FKT; kt++) {
                CP_WAIT(FSTAGES - 2);
                asm volatile("bar.sync 1, 256;" ::: "memory");
                const int s = kt % FSTAGES;
                int pf = kt + FSTAGES - 1;
                if (pf < FKT) {
                    int ps = pf % FSTAGES;
                    int koff = pf * FBK;
                    CP16(dA + ps*FSTB,               gA + koff);
                    CP16(dA + ps*FSTB + 64*FPITCH*2, gA + (size_t)64*KP2 + koff);
                    CP16(dB + ps*FSTB,               gB + koff);
                    CP16(dB + ps*FSTB + 64*FPITCH*2, gB + (size_t)64*KP2 + koff);
                }
                CP_COMMIT();

                const uint32_t aS = aBase + s * FSTB;
                const uint32_t bS = bBase + s * FSTB;
                #pragma unroll
                for (int ks = 0; ks < 2; ks++) {
                    uint32_t a[2][4];
                    #pragma unroll
                    for (int mt = 0; mt < 2; mt++)
                        ldsm4(a[mt][0], a[mt][1], a[mt][2], a[mt][3],
                              aS + (mt*16*FPITCH + ks*16) * 2);
                    uint32_t b[8][2];
                    #pragma unroll
                    for (int p = 0; p < 4; p++) {
                        uint32_t r0, r1, r2, r3;
                        ldsm4(r0, r1, r2, r3, bS + (p*16*FPITCH + ks*16) * 2);
                        b[2*p][0] = r0; b[2*p][1] = r1;
                        b[2*p+1][0] = r2; b[2*p+1][1] = r3;
                    }
                    #pragma unroll
                    for (int mt = 0; mt < 2; mt++)
                        #pragma unroll
                        for (int nt = 0; nt < 8; nt++)
                            mma16816(acc[mt][nt], a[mt], b[nt]);
                }
            }
            CP_WAIT(0);
            asm volatile("bar.sync 1, 256;" ::: "memory");

            #pragma unroll
            for (int mt = 0; mt < 2; mt++) {
                const int r0 = m0 + wm*32 + mt*16 + (lane >> 2);
                #pragma unroll
                for (int nt = 0; nt < 8; nt++) {
                    const int c = n0 + wn*64 + nt*8 + ((lane & 3) << 1);
                    if (c < NUM_CLASSES) {
                        float bb = __ldg(bias + c);
                        out[(size_t)r0      * NUM_CLASSES + c] = acc[mt][nt][0] + bb;
                        out[(size_t)(r0+8)  * NUM_CLASSES + c] = acc[mt][nt][2] + bb;
                    }
                    if (c + 1 < NUM_CLASSES) {
                        float bb = __ldg(bias + c + 1);
                        out[(size_t)r0      * NUM_CLASSES + c + 1] = acc[mt][nt][1] + bb;
                        out[(size_t)(r0+8)  * NUM_CLASSES + c + 1] = acc[mt][nt][3] + bb;
                    }
                }
            }
            asm volatile("bar.sync 1, 256;" ::: "memory");
        }
    }
#endif
}

// ============================================================================
typedef CUresult (*PFN_tmap)(CUtensorMap*, CUtensorMapDataType, cuuint32_t, void*,
                             const cuuint64_t*, const cuuint64_t*, const cuuint32_t*,
                             const cuuint32_t*, CUtensorMapInterleave, CUtensorMapSwizzle,
                             CUtensorMapL2promotion, CUtensorMapFloatOOBfill);

extern "C" void kernel_launch(void* const* d_in, const int* in_sizes, int n_in,
                              void* d_out, int out_size) {
    const float* x       = (const float*)d_in[0];
    const float* context = (const float*)d_in[1];
    const float* base_w  = (const float*)d_in[2];
    const float* base_b  = (const float*)d_in[3];
    const float* ctx_w   = (const float*)d_in[4];
    const float* ctx_b   = (const float*)d_in[5];
    const float* ln_g    = (const float*)d_in[6];
    const float* ln_b    = (const float*)d_in[7];
    const float* coeff_w = (const float*)d_in[8];
    const float* coeff_b = (const float*)d_in[9];
    const float* basis_A = (const float*)d_in[10];
    const float* basis_B = (const float*)d_in[11];
    float* out = (float*)d_out;
    (void)in_sizes; (void)n_in; (void)out_size;

    PFN_tmap encode = nullptr;
    cudaDriverEntryPointQueryResult qres;
    cudaGetDriverEntryPoint("cuTensorMapEncodeTiled", (void**)&encode,
                            cudaEnableDefault, &qres);

    void *pA = nullptr, *pB = nullptr;
    cudaGetSymbolAddress(&pA, g_Ah);
    cudaGetSymbolAddress(&pB, g_Bh);

    CUtensorMap tmA, tmB;
    if (encode) {
        cuuint64_t dimsA[3]    = {KP2, NB, 1};
        cuuint64_t stridesA[2] = {(cuuint64_t)KP2 * 2, (cuuint64_t)KP2 * 2 * NB};
        cuuint32_t box[3]      = {GBK, 128, 1};
        cuuint32_t es[3]       = {1, 1, 1};
        encode(&tmA, CU_TENSOR_MAP_DATA_TYPE_FLOAT16, 3, pA, dimsA, stridesA, box, es,
               CU_TENSOR_MAP_INTERLEAVE_NONE, CU_TENSOR_MAP_SWIZZLE_128B,
               CU_TENSOR_MAP_L2_PROMOTION_L2_128B, CU_TENSOR_MAP_FLOAT_OOB_FILL_NONE);
        cuuint64_t dimsB[3]    = {KP2, NPAD2, 1};
        cuuint64_t stridesB[2] = {(cuuint64_t)KP2 * 2, (cuuint64_t)KP2 * 2 * NPAD2};
        encode(&tmB, CU_TENSOR_MAP_DATA_TYPE_FLOAT16, 3, pB, dimsB, stridesB, box, es,
               CU_TENSOR_MAP_INTERLEAVE_NONE, CU_TENSOR_MAP_SWIZZLE_128B,
               CU_TENSOR_MAP_L2_PROMOTION_L2_128B, CU_TENSOR_MAP_FLOAT_OOB_FILL_NONE);
    }

    cudaFuncSetAttribute(gemm_tc, cudaFuncAttributeMaxDynamicSharedMemorySize, SMEM_TOTAL);

    prep<<<PREP_GRID, 256>>>(context, ctx_w, ctx_b, ln_g, ln_b,
                             coeff_w, coeff_b, x, basis_A, base_w, basis_B);

    gemm_tc<<<2 * NCLUSTERS, 320, SMEM_TOTAL>>>(tmA, tmB, base_b, out);
}

// round 16
// speedup vs baseline: 1.0398x; 1.0398x over previous
#include <cuda_runtime.h>
#include <cuda_fp16.h>
#include <cuda.h>
#include <math.h>
#include <stdint.h>

#define D_MODEL     2048
#define NUM_CLASSES 50257
#define NB          2048
#define HIDDEN      128
#define NBASIS      8
#define RANK        4
#define KP2         2112      // padded K: 33 * 64
#define NPAD2       50688     // padded N: 99 * 512
#define CHUNKS      264       // KP2 / 8
#define LN_EPS      1e-5f

// ---- tcgen05 persistent config: M256 x N512 cluster tile, 74 clusters ----
#define GBN         512
#define GBK         64
#define KTILES      33
#define NTILES      (8 * (NPAD2 / GBN))   // 792
#define NCLUSTERS   74
#define GSTAGES     4
#define STAGE_BYTES 49152     // A 16KB + B0 16KB + B1 16KB
#define OFF_TMEM    0
#define OFF_FULL    8
#define OFF_EMPTY   40
#define OFF_DONE    72        // epi_done (leader, count=2)
#define OFF_EPIF    80        // epi_full (per CTA, count=1)
#define OFF_TILE    1024
#define OFF_EPI     (OFF_TILE + GSTAGES * STAGE_BYTES)   // 197632
#define SMEM_TOTAL  (OFF_EPI + 8 * 4224)                 // 231424 (fits 232448)
#define IDESC       0x10400010u

// ---- prep kernel block roles: 2 rows per conv block (MLP 4, no division) ----
#define PREP_CTX    128
#define PREP_CX     (NB / 2)              // 1024 conv_x blocks (2 rows each)
#define PREP_CW     (NPAD2 / 2)           // 25344 conv_w blocks (2 rows each)
#define PREP_GRID   (PREP_CTX + PREP_CX + PREP_CW)
#define PREP_SMEM   27584

// ---- HMMA fallback tile config ----
#define FBM         128
#define FBK         32
#define FKT         66
#define FSTAGES     4
#define FPITCH      40
#define FSTB        (FBM * FPITCH * 2)

#if defined(__CUDA_ARCH_FEAT_SM103_ALL) || (__CUDA_ARCH_SPECIFIC__ == 1030)
#define HAS_TCGEN05 1
#else
#define HAS_TCGEN05 0
#endif

__device__ __half g_Ah[(size_t)NB * KP2];
__device__ __half g_Bh[(size_t)NPAD2 * KP2];

union H8 { __half h[8]; uint4 u; };

__device__ __forceinline__ void cvt8(H8& o, const float* p) {
    float4 v0 = *(const float4*)p;
    float4 v1 = *(const float4*)(p + 4);
    o.h[0]=__float2half_rn(v0.x); o.h[1]=__float2half_rn(v0.y);
    o.h[2]=__float2half_rn(v0.z); o.h[3]=__float2half_rn(v0.w);
    o.h[4]=__float2half_rn(v1.x); o.h[5]=__float2half_rn(v1.y);
    o.h[6]=__float2half_rn(v1.z); o.h[7]=__float2half_rn(v1.w);
}

// ============================================================================
// prep kernel: 2 rows per conv block (MLP 4, zero integer division)
// ============================================================================
__global__ __launch_bounds__(256) void prep(
        const float* __restrict__ ctx, const float* __restrict__ cw,
        const float* __restrict__ cb,  const float* __restrict__ lg,
        const float* __restrict__ lb,  const float* __restrict__ cfw,
        const float* __restrict__ cfb, const float* __restrict__ x,
        const float* __restrict__ A,
        const float* __restrict__ w,   const float* __restrict__ bB) {
    __shared__ char buf[PREP_SMEM];
    const int tid = threadIdx.x;
    const int bb = blockIdx.x;

    if (bb >= PREP_CTX + PREP_CX) {
        // ---- conv_w: 2 rows per block; thread tid = chunk of both rows ----
        const int r0 = (bb - PREP_CTX - PREP_CX) * 2;
        #pragma unroll
        for (int rep = 0; rep < 2; rep++) {
            const int row = r0 + rep;
            H8 o;
            if (row < NUM_CLASSES) {
                cvt8(o, w + (size_t)row * D_MODEL + tid * 8);
            } else {
                #pragma unroll
                for (int i = 0; i < 8; i++) o.h[i] = __float2half_rn(0.f);
            }
            *(uint4*)(g_Bh + (size_t)row * KP2 + tid * 8) = o.u;
        }
        if (tid < 16) {          // tail chunks 256..263 for both rows
            const int rep = tid >> 3, tt = tid & 7;
            const int row = r0 + rep;
            H8 t;
            if (row < NUM_CLASSES && tt < 4) {
                int nn = tt * 2;
                float4 a = *(const float4*)(bB + ((size_t)nn       * NUM_CLASSES + row) * 4);
                float4 b = *(const float4*)(bB + ((size_t)(nn + 1) * NUM_CLASSES + row) * 4);
                t.h[0]=__float2half_rn(a.x); t.h[1]=__float2half_rn(a.y);
                t.h[2]=__float2half_rn(a.z); t.h[3]=__float2half_rn(a.w);
                t.h[4]=__float2half_rn(b.x); t.h[5]=__float2half_rn(b.y);
                t.h[6]=__float2half_rn(b.z); t.h[7]=__float2half_rn(b.w);
            } else {
                #pragma unroll
                for (int i = 0; i < 8; i++) t.h[i] = __float2half_rn(0.f);
            }
            *(uint4*)(g_Bh + (size_t)row * KP2 + (256 + tt) * 8) = t.u;
        }
        return;
    }

    if (bb >= PREP_CTX) {
        // ---- conv_x: 2 rows per block ----
        const int r0 = (bb - PREP_CTX) * 2;
        #pragma unroll
        for (int rep = 0; rep < 2; rep++) {
            const int row = r0 + rep;
            H8 o;
            cvt8(o, x + (size_t)row * D_MODEL + tid * 8);
            *(uint4*)(g_Ah + (size_t)row * KP2 + tid * 8) = o.u;
        }
        if (tid < 16) {          // pad chunks 256..263 (lora overwrites 2048..2079 later)
            const int rep = tid >> 3, tt = tid & 7;
            const int row = r0 + rep;
            H8 t;
            #pragma unroll
            for (int i = 0; i < 8; i++) t.h[i] = __float2half_rn(0.f);
            *(uint4*)(g_Ah + (size_t)row * KP2 + (256 + tt) * 8) = t.u;
        }
        return;
    }

    // ---- fused ctx chain ----
    float* Ws  = (float*)buf;
    float* Xs  = (float*)(buf + 16384);
    float* As  = (float*)buf;
    float* Xs2 = (float*)(buf + 16512);
    float* cfs = (float*)(buf + 24960);
    float* ys  = (float*)(buf + 25472);

    const int tn = tid & 31;
    const int tm = tid >> 5;
    const int b0 = bb * 16;

    float acc[2][4];
    #pragma unroll
    for (int i = 0; i < 2; i++)
        #pragma unroll
        for (int j = 0; j < 4; j++) acc[i][j] = 0.f;

    for (int k0 = 0; k0 < D_MODEL; k0 += 32) {
        if (tid < 128) {
            int row = tid >> 3, c4 = tid & 7;
            *(float4*)&Xs[row * 36 + c4 * 4] =
                *(const float4*)(ctx + (size_t)(b0 + row) * D_MODEL + k0 + c4 * 4);
        }
        #pragma unroll
        for (int i = 0; i < 4; i++) {
            int idx = tid + i * 256;
            int j = idx >> 3, c4 = idx & 7;
            float4 v = *(const float4*)(cw + (size_t)j * D_MODEL + k0 + c4 * 4);
            Ws[(c4*4+0)*128 + j] = v.x;
            Ws[(c4*4+1)*128 + j] = v.y;
            Ws[(c4*4+2)*128 + j] = v.z;
            Ws[(c4*4+3)*128 + j] = v.w;
        }
        __syncthreads();
        #pragma unroll 8
        for (int kk = 0; kk < 32; kk++) {
            float x0 = Xs[(tm*2)*36 + kk], x1 = Xs[(tm*2+1)*36 + kk];
            float4 wv = *(const float4*)&Ws[kk*128 + tn*4];
            acc[0][0] += x0*wv.x; acc[0][1] += x0*wv.y;
            acc[0][2] += x0*wv.z; acc[0][3] += x0*wv.w;
            acc[1][0] += x1*wv.x; acc[1][1] += x1*wv.y;
            acc[1][2] += x1*wv.z; acc[1][3] += x1*wv.w;
        }
        __syncthreads();
    }
    {
        float4 cbv = *(const float4*)(cb + tn * 4);
        #pragma unroll
        for (int mi = 0; mi < 2; mi++) {
            acc[mi][0] += cbv.x; acc[mi][1] += cbv.y;
            acc[mi][2] += cbv.z; acc[mi][3] += cbv.w;
        }
    }

    float4 lgv = *(const float4*)(lg + tn * 4);
    float4 lbv = *(const float4*)(lb + tn * 4);
    #pragma unroll
    for (int mi = 0; mi < 2; mi++) {
        float s = acc[mi][0]+acc[mi][1]+acc[mi][2]+acc[mi][3];
        float s2 = acc[mi][0]*acc[mi][0]+acc[mi][1]*acc[mi][1]
                 + acc[mi][2]*acc[mi][2]+acc[mi][3]*acc[mi][3];
        #pragma unroll
        for (int o = 16; o > 0; o >>= 1) {
            s  += __shfl_xor_sync(0xffffffffu, s,  o);
            s2 += __shfl_xor_sync(0xffffffffu, s2, o);
        }
        float mu = s * (1.f/128.f);
        float var = s2 * (1.f/128.f) - mu*mu;
        float rstd = rsqrtf(var + LN_EPS);
        float g[4];
        const float* lgp = (const float*)&lgv;
        const float* lbp = (const float*)&lbv;
        #pragma unroll
        for (int ni = 0; ni < 4; ni++) {
            float hn = (acc[mi][ni] - mu) * rstd * lgp[ni] + lbp[ni];
            g[ni] = 0.5f * hn * (1.f + erff(hn * 0.70710678118654752f));
        }
        #pragma unroll
        for (int n = 0; n < NBASIS; n++) {
            float4 wv = *(const float4*)(cfw + n * HIDDEN + tn * 4);
            float p = g[0]*wv.x + g[1]*wv.y + g[2]*wv.z + g[3]*wv.w;
            #pragma unroll
            for (int o = 16; o > 0; o >>= 1) p += __shfl_xor_sync(0xffffffffu, p, o);
            if (tn == 0) cfs[(tm*2+mi)*8 + n] = p + cfb[n];
        }
    }
    __syncthreads();

    float y0 = 0.f, y1 = 0.f;
    for (int k0 = 0; k0 < D_MODEL; k0 += 128) {
        #pragma unroll
        for (int i = 0; i < 4; i++) {
            int idx = tid + i * 256;
            int j = idx >> 5, c4 = idx & 31;
            float4 v = *(const float4*)(A + (size_t)j * D_MODEL + k0 + c4 * 4);
            float* dst = &As[j * 129 + c4 * 4];
            dst[0] = v.x; dst[1] = v.y; dst[2] = v.z; dst[3] = v.w;
        }
        #pragma unroll
        for (int i = 0; i < 2; i++) {
            int idx = tid + i * 256;
            int r = idx >> 5, c4 = idx & 31;
            *(float4*)&Xs2[r * 132 + c4 * 4] =
                *(const float4*)(x + (size_t)(b0 + r) * D_MODEL + k0 + c4 * 4);
        }
        __syncthreads();
        const float* ar = As + tn * 129;
        const float* x0p = Xs2 + (tm*2) * 132;
        const float* x1p = Xs2 + (tm*2+1) * 132;
        #pragma unroll 16
        for (int kk = 0; kk < 128; kk++) {
            float a = ar[kk];
            y0 += a * x0p[kk];
            y1 += a * x1p[kk];
        }
        __syncthreads();
    }
    ys[(tm*2)*33 + tn]   = y0;
    ys[(tm*2+1)*33 + tn] = y1;
    __syncthreads();

    if (tid < 64) {
        int row = tid >> 2, r = tid & 3;
        float cfr[8], z = 0.f;
        #pragma unroll
        for (int n = 0; n < 8; n++) {
            cfr[n] = cfs[row*8 + n];
            z += cfr[n] * ys[row*33 + n*4 + r];
        }
        #pragma unroll
        for (int n = 0; n < 8; n++)
            g_Ah[(size_t)(b0 + row) * KP2 + D_MODEL + n*4 + r] = __float2half_rn(cfr[n] * z);
    }
}

// ============================================================================
// helpers
// ============================================================================
__device__ __forceinline__ uint32_t smem_u32(const void* p) {
    return (uint32_t)__cvta_generic_to_shared(p);
}
__device__ __forceinline__ void mbar_init(uint32_t a, uint32_t cnt) {
    asm volatile("mbarrier.init.shared.b64 [%0], %1;" :: "r"(a), "r"(cnt) : "memory");
}
__device__ __forceinline__ void mbar_expect_tx(uint32_t a, uint32_t bytes) {
    asm volatile("mbarrier.arrive.expect_tx.shared.b64 _, [%0], %1;" :: "r"(a), "r"(bytes) : "memory");
}
__device__ __forceinline__ void mbar_wait(uint32_t a, uint32_t parity) {
    asm volatile(
        "{\n\t.reg .pred P1;\n\t"
        "WL_%=:\n\t"
        "mbarrier.try_wait.parity.acquire.cta.shared::cta.b64 P1, [%0], %1, 0x989680;\n\t"
        "@P1 bra.uni WD_%=;\n\t"
        "bra.uni WL_%=;\n\t"
        "WD_%=:\n\t}" :: "r"(a), "r"(parity) : "memory");
}
__device__ __forceinline__ void mbar_wait_relaxed(uint32_t a, uint32_t parity) {
    asm volatile(
        "{\n\t.reg .pred P1;\n\t"
        "WL_%=:\n\t"
        "mbarrier.try_wait.parity.relaxed.cta.shared::cta.b64 P1, [%0], %1, 0x989680;\n\t"
        "@P1 bra.uni WD_%=;\n\t"
        "bra.uni WL_%=;\n\t"
        "WD_%=:\n\t}" :: "r"(a), "r"(parity) : "memory");
}
__device__ __forceinline__ uint32_t elect_one() {
    uint32_t pred;
    asm volatile("{\n\t.reg .pred p;\n\telect.sync _|p, 0xFFFFFFFF;\n\t"
                 "selp.b32 %0, 1, 0, p;\n\t}" : "=r"(pred));
    return pred;
}
__device__ __forceinline__ uint32_t ctarank() {
    uint32_t r; asm("mov.u32 %0, %%cluster_ctarank;" : "=r"(r)); return r;
}
__device__ __forceinline__ void mbar_arrive_leader(uint32_t a) {
    asm volatile(
        "{\n\t.reg .b32 la;\n\tand.b32 la, %0, 0xFEFFFFFF;\n\t"
        "mbarrier.arrive.shared::cluster.b64 _, [la];\n\t}"
        :: "r"(a) : "memory");
}

#define CP16(d, s)  asm volatile("cp.async.cg.shared.global [%0], [%1], 16;" :: "r"(d), "l"(s))
#define CP_COMMIT() asm volatile("cp.async.commit_group;")
#define CP_WAIT(n)  asm volatile("cp.async.wait_group %0;" :: "n"(n))
__device__ __forceinline__ void ldsm4(uint32_t& r0, uint32_t& r1, uint32_t& r2, uint32_t& r3, uint32_t a) {
    asm volatile("ldmatrix.sync.aligned.m8n8.x4.shared.b16 {%0,%1,%2,%3}, [%4];"
                 : "=r"(r0), "=r"(r1), "=r"(r2), "=r"(r3) : "r"(a));
}
__device__ __forceinline__ void mma16816(float* c, const uint32_t* a, const uint32_t* b) {
    asm volatile("mma.sync.aligned.m16n8k16.row.col.f32.f16.f16.f32 "
                 "{%0,%1,%2,%3}, {%4,%5,%6,%7}, {%8,%9}, {%0,%1,%2,%3};"
                 : "+f"(c[0]), "+f"(c[1]), "+f"(c[2]), "+f"(c[3])
                 : "r"(a[0]), "r"(a[1]), "r"(a[2]), "r"(a[3]), "r"(b[0]), "r"(b[1]));
}

// ============================================================================
// persistent main GEMM: 74 clusters, M256xN512 tiles, 320 threads
// warps 0-7 epilogue, warp 8 producer, warp 9 consumer (+TMEM alloc)
// (byte-identical to the R14 passing version, 333.7us)
// ============================================================================
__global__ void __launch_bounds__(320, 1) __cluster_dims__(2, 1, 1)
gemm_tc(const __grid_constant__ CUtensorMap tmA,
        const __grid_constant__ CUtensorMap tmB,
        const float* __restrict__ bias,
        float* __restrict__ out) {
    extern __shared__ char smem[];
#if HAS_TCGEN05
    const uint32_t sb = smem_u32(smem);
    const int tid = threadIdx.x;
    const int wid = tid >> 5;
    const int lane = tid & 31;
    const uint32_t rank = ctarank();
    const int cid = blockIdx.x >> 1;

    if (tid == 0) {
        #pragma unroll
        for (int s = 0; s < GSTAGES; s++) {
            mbar_init(sb + OFF_FULL  + s * 8, 1);
            mbar_init(sb + OFF_EMPTY + s * 8, 1);
        }
        mbar_init(sb + OFF_DONE, 2);   // epi_done: one arrive per CTA
        mbar_init(sb + OFF_EPIF, 1);   // epi_full: multicast commit
    }
    if (wid == 9) {
        asm volatile("tcgen05.alloc.cta_group::2.sync.aligned.shared::cta.b32 [%0], %1;"
                     :: "r"(sb + OFF_TMEM), "r"(512u) : "memory");
    }
    __syncthreads();
    uint32_t tbase;
    asm volatile("ld.shared.b32 %0, [%1];" : "=r"(tbase) : "r"(sb + OFF_TMEM));

    asm volatile("barrier.cluster.arrive.aligned;" ::: "memory");
    asm volatile("barrier.cluster.wait.aligned;" ::: "memory");

    // ---- producer: warp 8 lane 0 in BOTH CTAs, continuous stage ring ----
    if (tid == 256) {
        int pphase = 1, pstage = 0;
        for (int t = cid; t < NTILES; t += NCLUSTERS) {
            const int arow = (t & 7) * 256 + (int)rank * 128;
            const int n0   = (t >> 3) * GBN;
            for (int kt = 0; kt < KTILES; kt++) {
                mbar_wait_relaxed(sb + OFF_EMPTY + pstage * 8, (uint32_t)pphase);
                if (rank == 0) mbar_expect_tx(sb + OFF_FULL + pstage * 8, 2 * STAGE_BYTES);
                const int k0 = kt * GBK;
                const uint32_t st = sb + OFF_TILE + pstage * STAGE_BYTES;
                const uint32_t fb = sb + OFF_FULL + pstage * 8;
                asm volatile(
                    "{\n\t.reg .b32 lb;\n\tand.b32 lb, %5, 0xFEFFFFFF;\n\t"
                    "cp.async.bulk.tensor.3d.cta_group::2.shared::cluster.global"
                    ".tile.mbarrier::complete_tx::bytes [%0], [%1, {%2, %3, %4}], [lb];\n\t}"
                    :: "r"(st), "l"(&tmA), "r"(k0), "r"(arow), "r"(0), "r"(fb) : "memory");
                asm volatile(
                    "{\n\t.reg .b32 lb;\n\tand.b32 lb, %5, 0xFEFFFFFF;\n\t"
                    "cp.async.bulk.tensor.3d.cta_group::2.shared::cluster.global"
                    ".tile.mbarrier::complete_tx::bytes [%0], [%1, {%2, %3, %4}], [lb];\n\t}"
                    :: "r"(st + 16384), "l"(&tmB), "r"(k0), "r"(n0 + (int)rank * 128), "r"(0), "r"(fb) : "memory");
                asm volatile(
                    "{\n\t.reg .b32 lb;\n\tand.b32 lb, %5, 0xFEFFFFFF;\n\t"
                    "cp.async.bulk.tensor.3d.cta_group::2.shared::cluster.global"
                    ".tile.mbarrier::complete_tx::bytes [%0], [%1, {%2, %3, %4}], [lb];\n\t}"
                    :: "r"(st + 32768), "l"(&tmB), "r"(k0), "r"(n0 + 256 + (int)rank * 128), "r"(0), "r"(fb) : "memory");
                if (++pstage == GSTAGES) { pstage = 0; pphase ^= 1; }
            }
        }
    }

    // ---- consumer: warp 9, leader CTA, one elected thread ----
    if (wid == 9 && rank == 0) {
        if (elect_one()) {
            int cphase = 0, cstage = 0, ti = 0;
            for (int t = cid; t < NTILES; t += NCLUSTERS, ti++) {
                if (ti > 0) {
                    mbar_wait(sb + OFF_DONE, (uint32_t)((ti - 1) & 1));
                    asm volatile("tcgen05.fence::after_thread_sync;" ::: "memory");
                }
                for (int kt = 0; kt < KTILES; kt++) {
                    mbar_wait(sb + OFF_FULL + cstage * 8, (uint32_t)cphase);
                    const uint32_t st = sb + OFF_TILE + cstage * STAGE_BYTES;
                    const uint64_t dbase = (uint64_t(2) << 61) | (uint64_t(1) << 46)
                                         | (uint64_t(64) << 32) | (uint64_t(1) << 16);
                    const uint64_t ad  = dbase | ((uint64_t)(st >> 4) & 0x3FFF);
                    const uint64_t bd0 = dbase | ((uint64_t)((st + 16384) >> 4) & 0x3FFF);
                    const uint64_t bd1 = dbase | ((uint64_t)((st + 32768) >> 4) & 0x3FFF);
                    #pragma unroll
                    for (int ks = 0; ks < 4; ks++) {
                        uint32_t en = (kt | ks) ? 1u : 0u;
                        asm volatile(
                            "{\n\t.reg .pred p;\n\tsetp.ne.u32 p, %5, 0;\n\t"
                            "tcgen05.mma.cta_group::2.kind::f16 [%0], %1, %2, %3, "
                            "{%4,%4,%4,%4,%4,%4,%4,%4}, p;\n\t}"
                            :: "r"(tbase), "l"(ad + ks*2), "l"(bd0 + ks*2), "r"(IDESC), "r"(0u), "r"(en) : "memory");
                        asm volatile(
                            "{\n\t.reg .pred p;\n\tsetp.ne.u32 p, %5, 0;\n\t"
                            "tcgen05.mma.cta_group::2.kind::f16 [%0], %1, %2, %3, "
                            "{%4,%4,%4,%4,%4,%4,%4,%4}, p;\n\t}"
                            :: "r"(tbase + 256), "l"(ad + ks*2), "l"(bd1 + ks*2), "r"(IDESC), "r"(0u), "r"(en) : "memory");
                    }
                    asm volatile(
                        "tcgen05.commit.cta_group::2.mbarrier::arrive::one.shared::cluster"
                        ".multicast::cluster.b64 [%0], %1;"
                        :: "r"(sb + OFF_EMPTY + cstage * 8), "h"((uint16_t)3) : "memory");
                    if (++cstage == GSTAGES) { cstage = 0; cphase ^= 1; }
                }
                asm volatile(
                    "tcgen05.commit.cta_group::2.mbarrier::arrive::one.shared::cluster"
                    ".multicast::cluster.b64 [%0], %1;"
                    :: "r"(sb + OFF_EPIF), "h"((uint16_t)3) : "memory");
            }
        }
    }

    // ---- epilogue: warps 0..7, both CTAs ----
    if (wid < 8) {
        const int sub  = wid & 3;       // TMEM subpartition (warp % 4)
        const int half = wid >> 2;      // column half of the 512
        float* tsm = (float*)(smem + OFF_EPI + wid * 4224);   // 32 x 33 fp32
        int ti = 0;
        for (int t = cid; t < NTILES; t += NCLUSTERS, ti++) {
            mbar_wait(sb + OFF_EPIF, (uint32_t)(ti & 1));
            asm volatile("tcgen05.fence::after_thread_sync;" ::: "memory");
            const int rowbase = (t & 7) * 256 + (int)rank * 128 + sub * 32;
            const int n0 = (t >> 3) * GBN;
            #pragma unroll 1
            for (int i = 0; i < 8; i++) {
                const int blk = half * 8 + i;
                const int cbase = n0 + blk * 32;
                if (cbase < NUM_CLASSES) {
                    uint32_t r[32];
                    asm volatile(
                        "tcgen05.ld.sync.aligned.32x32b.x32.b32 "
                        "{%0,%1,%2,%3,%4,%5,%6,%7,%8,%9,%10,%11,%12,%13,%14,%15,"
                        "%16,%17,%18,%19,%20,%21,%22,%23,%24,%25,%26,%27,%28,%29,%30,%31}, [%32];"
                        : "=r"(r[0]),"=r"(r[1]),"=r"(r[2]),"=r"(r[3]),"=r"(r[4]),"=r"(r[5]),
                          "=r"(r[6]),"=r"(r[7]),"=r"(r[8]),"=r"(r[9]),"=r"(r[10]),"=r"(r[11]),
                          "=r"(r[12]),"=r"(r[13]),"=r"(r[14]),"=r"(r[15]),"=r"(r[16]),"=r"(r[17]),
                          "=r"(r[18]),"=r"(r[19]),"=r"(r[20]),"=r"(r[21]),"=r"(r[22]),"=r"(r[23]),
                          "=r"(r[24]),"=r"(r[25]),"=r"(r[26]),"=r"(r[27]),"=r"(r[28]),"=r"(r[29]),
                          "=r"(r[30]),"=r"(r[31])
                        : "r"(tbase + blk * 32));
                    asm volatile("tcgen05.wait::ld.sync.aligned;" ::: "memory");
                    #pragma unroll
                    for (int j = 0; j < 32; j++) tsm[lane * 33 + j] = __uint_as_float(r[j]);
                    __syncwarp();
                    const int c = cbase + lane;
                    const bool ok = (c < NUM_CLASSES);
                    const float bv = ok ? __ldg(bias + c) : 0.f;
                    #pragma unroll 8
                    for (int rr = 0; rr < 32; rr++) {
                        float v = tsm[rr * 33 + lane] + bv;
                        if (ok) out[(size_t)(rowbase + rr) * NUM_CLASSES + c] = v;
                    }
                    __syncwarp();
                }
            }
            // all 8 epi warps of this CTA done -> arrive leader's epi_done
            asm volatile("bar.sync 3, 256;" ::: "memory");
            if (tid == 0) mbar_arrive_leader(sb + OFF_DONE);
        }
    }

    __syncthreads();
    if (wid == 9) {
        asm volatile("tcgen05.relinquish_alloc_permit.cta_group::2.sync.aligned;");
        asm volatile("tcgen05.dealloc.cta_group::2.sync.aligned.b32 %0, %1;"
                     :: "r"(tbase), "r"(512u));
    }
    asm volatile("barrier.cluster.arrive.aligned;" ::: "memory");
    asm volatile("barrier.cluster.wait.aligned;" ::: "memory");

#else  // ================= mma.sync fallback (base sm_103 cubin) =============
    const int tid  = threadIdx.x;
    const int lane = tid & 31;
    const int wid  = tid >> 5;
    if (wid < 8) {
        const int wm   = wid & 3;
        const int wn   = wid >> 2;

        __half* As = (__half*)smem;
        __half* Bs = (__half*)smem + (size_t)FSTAGES * FBM * FPITCH;
        const uint32_t sA = smem_u32(As), sB = smem_u32(Bs);

        const int crow = tid >> 2, cch = tid & 3;
        const uint32_t dA = sA + (crow * FPITCH + cch * 8) * 2;
        const uint32_t dB = sB + (crow * FPITCH + cch * 8) * 2;

        const int aRow = wm*32 + (lane & 15);
        const int aCol = (lane >> 4) << 3;
        const int bRow = wn*64 + (lane & 7) + ((lane >> 4) << 3);
        const int bCol = ((lane >> 3) & 1) << 3;
        const uint32_t aBase = sA + (aRow * FPITCH + aCol) * 2;
        const uint32_t bBase = sB + (bRow * FPITCH + bCol) * 2;

        const int FT = 16 * (NPAD2 / 128);
        for (int t = blockIdx.x; t < FT; t += gridDim.x) {
            const int m0 = (t & 15) * FBM;
            const int n0 = (t >> 4) * 128;
            const __half* gA = g_Ah + (size_t)(m0 + crow) * KP2 + cch * 8;
            const __half* gB = g_Bh + (size_t)(n0 + crow) * KP2 + cch * 8;

            float acc[2][8][4];
            #pragma unroll
            for (int i = 0; i < 2; i++)
                #pragma unroll
                for (int j = 0; j < 8; j++)
                    #pragma unroll
                    for (int k = 0; k < 4; k++) acc[i][j][k] = 0.f;

            #pragma unroll
            for (int s = 0; s < FSTAGES - 1; s++) {
                int koff = s * FBK;
                CP16(dA + s*FSTB,                 gA + koff);
                CP16(dA + s*FSTB + 64*FPITCH*2,   gA + (size_t)64*KP2 + koff);
                CP16(dB + s*FSTB,                 gB + koff);
                CP16(dB + s*FSTB + 64*FPITCH*2,   gB + (size_t)64*KP2 + koff);
                CP_COMMIT();
            }

            #pragma unroll 1
            for (int kt = 0; kt < FKT; kt++) {
                CP_WAIT(FSTAGES - 2);
                asm volatile("bar.sync 1, 256;" ::: "memory");
                const int s = kt % FSTAGES;
                int pf = kt + FSTAGES - 1;
                if (pf < FKT) {
                    int ps = pf % FSTAGES;
                    int koff = pf * FBK;
                    CP16(dA + ps*FSTB,               gA + koff);
                    CP16(dA + ps*FSTB + 64*FPITCH*2, gA + (size_t)64*KP2 + koff);
                    CP16(dB + ps*FSTB,               gB + koff);
                    CP16(dB + ps*FSTB + 64*FPITCH*2, gB + (size_t)64*KP2 + koff);
                }
                CP_COMMIT();

                const uint32_t aS = aBase + s * FSTB;
                const uint32_t bS = bBase + s * FSTB;
                #pragma unroll
                for (int ks = 0; ks < 2; ks++) {
                    uint32_t a[2][4];
                    #pragma unroll
                    for (int mt = 0; mt < 2; mt++)
                        ldsm4(a[mt][0], a[mt][1], a[mt][2], a[mt][3],
                              aS + (mt*16*FPITCH + ks*16) * 2);
                    uint32_t b[8][2];
                    #pragma unroll
                    for (int p = 0; p < 4; p++) {
                        uint32_t r0, r1, r2, r3;
                        ldsm4(r0, r1, r2, r3, bS + (p*16*FPITCH + ks*16) * 2);
                        b[2*p][0] = r0; b[2*p][1] = r1;
                        b[2*p+1][0] = r2; b[2*p+1][1] = r3;
                    }
                    #pragma unroll
                    for (int mt = 0; mt < 2; mt++)
                        #pragma unroll
                        for (int nt = 0; nt < 8; nt++)
                            mma16816(acc[mt][nt], a[mt], b[nt]);
                }
            }
            CP_WAIT(0);
            asm volatile("bar.sync 1, 256;" ::: "memory");

            #pragma unroll
            for (int mt = 0; mt < 2; mt++) {
                const int r0 = m0 + wm*32 + mt*16 + (lane >> 2);
                #pragma unroll
                for (int nt = 0; nt < 8; nt++) {
                    const int c = n0 + wn*64 + nt*8 + ((lane & 3) << 1);
                    if (c < NUM_CLASSES) {
                        float bb = __ldg(bias + c);
                        out[(size_t)r0      * NUM_CLASSES + c] = acc[mt][nt][0] + bb;
                        out[(size_t)(r0+8)  * NUM_CLASSES + c] = acc[mt][nt][2] + bb;
                    }
                    if (c + 1 < NUM_CLASSES) {
                        float bb = __ldg(bias + c + 1);
                        out[(size_t)r0      * NUM_CLASSES + c + 1] = acc[mt][nt][1] + bb;
                        out[(size_t)(r0+8)  * NUM_CLASSES + c + 1] = acc[mt][nt][3] + bb;
                    }
                }
            }
            asm volatile("bar.sync 1, 256;" ::: "memory");
        }
    }
#endif
}

// ============================================================================
typedef CUresult (*PFN_tmap)(CUtensorMap*, CUtensorMapDataType, cuuint32_t, void*,
                             const cuuint64_t*, const cuuint64_t*, const cuuint32_t*,
                             const cuuint32_t*, CUtensorMapInterleave, CUtensorMapSwizzle,
                             CUtensorMapL2promotion, CUtensorMapFloatOOBfill);

extern "C" void kernel_launch(void* const* d_in, const int* in_sizes, int n_in,
                              void* d_out, int out_size) {
    const float* x       = (const float*)d_in[0];
    const float* context = (const float*)d_in[1];
    const float* base_w  = (const float*)d_in[2];
    const float* base_b  = (const float*)d_in[3];
    const float* ctx_w   = (const float*)d_in[4];
    const float* ctx_b   = (const float*)d_in[5];
    const float* ln_g    = (const float*)d_in[6];
    const float* ln_b    = (const float*)d_in[7];
    const float* coeff_w = (const float*)d_in[8];
    const float* coeff_b = (const float*)d_in[9];
    const float* basis_A = (const float*)d_in[10];
    const float* basis_B = (const float*)d_in[11];
    float* out = (float*)d_out;
    (void)in_sizes; (void)n_in; (void)out_size;

    PFN_tmap encode = nullptr;
    cudaDriverEntryPointQueryResult qres;
    cudaGetDriverEntryPoint("cuTensorMapEncodeTiled", (void**)&encode,
                            cudaEnableDefault, &qres);

    void *pA = nullptr, *pB = nullptr;
    cudaGetSymbolAddress(&pA, g_Ah);
    cudaGetSymbolAddress(&pB, g_Bh);

    CUtensorMap tmA, tmB;
    if (encode) {
        cuuint64_t dimsA[3]    = {KP2, NB, 1};
        cuuint64_t stridesA[2] = {(cuuint64_t)KP2 * 2, (cuuint64_t)KP2 * 2 * NB};
        cuuint32_t box[3]      = {GBK, 128, 1};
        cuuint32_t es[3]       = {1, 1, 1};
        encode(&tmA, CU_TENSOR_MAP_DATA_TYPE_FLOAT16, 3, pA, dimsA, stridesA, box, es,
               CU_TENSOR_MAP_INTERLEAVE_NONE, CU_TENSOR_MAP_SWIZZLE_128B,
               CU_TENSOR_MAP_L2_PROMOTION_L2_128B, CU_TENSOR_MAP_FLOAT_OOB_FILL_NONE);
        cuuint64_t dimsB[3]    = {KP2, NPAD2, 1};
        cuuint64_t stridesB[2] = {(cuuint64_t)KP2 * 2, (cuuint64_t)KP2 * 2 * NPAD2};
        encode(&tmB, CU_TENSOR_MAP_DATA_TYPE_FLOAT16, 3, pB, dimsB, stridesB, box, es,
               CU_TENSOR_MAP_INTERLEAVE_NONE, CU_TENSOR_MAP_SWIZZLE_128B,
               CU_TENSOR_MAP_L2_PROMOTION_L2_128B, CU_TENSOR_MAP_FLOAT_OOB_FILL_NONE);
    }

    cudaFuncSetAttribute(gemm_tc, cudaFuncAttributeMaxDynamicSharedMemorySize, SMEM_TOTAL);

    prep<<<PREP_GRID, 256>>>(context, ctx_w, ctx_b, ln_g, ln_b,
                             coeff_w, coeff_b, x, basis_A, base_w, basis_B);

    gemm_tc<<<2 * NCLUSTERS, 320, SMEM_TOTAL>>>(tmA, tmB, base_b, out);
}

// round 17
// speedup vs baseline: 1.1447x; 1.1009x over previous
#include <cuda_runtime.h>
#include <cuda_fp16.h>
#include <cuda.h>
#include <math.h>
#include <stdint.h>

#define D_MODEL     2048
#define NUM_CLASSES 50257
#define NB          2048
#define HIDDEN      128
#define NBASIS      8
#define RANK        4
#define KP2         2112      // padded K: 33 * 64
#define NPAD2       50688     // padded N: 99 * 512
#define CHUNKS      264       // KP2 / 8
#define LN_EPS      1e-5f

// ---- tcgen05 persistent config: M256 x N512 tile, half-tile pipelined ----
#define GBN         512
#define GBK         64
#define KTILES      33
#define NTILES      (8 * (NPAD2 / GBN))   // 792
#define NCLUSTERS   74
#define GSTAGES     6
#define STAGE_BYTES 32768     // A 16KB + B(half) 16KB
#define OFF_TMEM    0
#define OFF_FULL    8                      // 6 x 8 = 48
#define OFF_EMPTY   56                     // 6 x 8 = 48
#define OFF_DONE0   104
#define OFF_DONE1   112
#define OFF_EPIF0   120
#define OFF_EPIF1   128
#define OFF_TILE    1024
#define OFF_EPI     (OFF_TILE + GSTAGES * STAGE_BYTES)   // 197632
#define SMEM_TOTAL  (OFF_EPI + 8 * 4224)                 // 231424 (fits 232448)
#define IDESC       0x10400010u            // F32 out, M=256, N=256

// ---- prep kernel block roles: 2 rows per conv block ----
#define PREP_CTX    128
#define PREP_CX     (NB / 2)
#define PREP_CW     (NPAD2 / 2)
#define PREP_GRID   (PREP_CTX + PREP_CX + PREP_CW)
#define PREP_SMEM   27584

// ---- HMMA fallback tile config ----
#define FBM         128
#define FBK         32
#define FKT         66
#define FSTAGES     4
#define FPITCH      40
#define FSTB        (FBM * FPITCH * 2)

#if defined(__CUDA_ARCH_FEAT_SM103_ALL) || (__CUDA_ARCH_SPECIFIC__ == 1030)
#define HAS_TCGEN05 1
#else
#define HAS_TCGEN05 0
#endif

__device__ __half g_Ah[(size_t)NB * KP2];
__device__ __half g_Bh[(size_t)NPAD2 * KP2];

union H8 { __half h[8]; __half2 h2[4]; uint4 u; };

// packed fp32 -> fp16 conversion: 4 F2FP.PACK instead of 8 scalar cvt
__device__ __forceinline__ void cvt8(H8& o, const float* p) {
    float4 v0 = *(const float4*)p;
    float4 v1 = *(const float4*)(p + 4);
    o.h2[0] = __float22half2_rn(make_float2(v0.x, v0.y));
    o.h2[1] = __float22half2_rn(make_float2(v0.z, v0.w));
    o.h2[2] = __float22half2_rn(make_float2(v1.x, v1.y));
    o.h2[3] = __float22half2_rn(make_float2(v1.z, v1.w));
}

// ============================================================================
// prep kernel: 2 rows per conv block, packed conversion
// ============================================================================
__global__ __launch_bounds__(256) void prep(
        const float* __restrict__ ctx, const float* __restrict__ cw,
        const float* __restrict__ cb,  const float* __restrict__ lg,
        const float* __restrict__ lb,  const float* __restrict__ cfw,
        const float* __restrict__ cfb, const float* __restrict__ x,
        const float* __restrict__ A,
        const float* __restrict__ w,   const float* __restrict__ bB) {
    __shared__ char buf[PREP_SMEM];
    const int tid = threadIdx.x;
    const int bb = blockIdx.x;

    if (bb >= PREP_CTX + PREP_CX) {
        const int r0 = (bb - PREP_CTX - PREP_CX) * 2;
        #pragma unroll
        for (int rep = 0; rep < 2; rep++) {
            const int row = r0 + rep;
            H8 o;
            if (row < NUM_CLASSES) {
                cvt8(o, w + (size_t)row * D_MODEL + tid * 8);
            } else {
                #pragma unroll
                for (int i = 0; i < 4; i++) o.h2[i] = __float22half2_rn(make_float2(0.f, 0.f));
            }
            *(uint4*)(g_Bh + (size_t)row * KP2 + tid * 8) = o.u;
        }
        if (tid < 16) {
            const int rep = tid >> 3, tt = tid & 7;
            const int row = r0 + rep;
            H8 t;
            if (row < NUM_CLASSES && tt < 4) {
                int nn = tt * 2;
                float4 a = *(const float4*)(bB + ((size_t)nn       * NUM_CLASSES + row) * 4);
                float4 b = *(const float4*)(bB + ((size_t)(nn + 1) * NUM_CLASSES + row) * 4);
                t.h2[0] = __float22half2_rn(make_float2(a.x, a.y));
                t.h2[1] = __float22half2_rn(make_float2(a.z, a.w));
                t.h2[2] = __float22half2_rn(make_float2(b.x, b.y));
                t.h2[3] = __float22half2_rn(make_float2(b.z, b.w));
            } else {
                #pragma unroll
                for (int i = 0; i < 4; i++) t.h2[i] = __float22half2_rn(make_float2(0.f, 0.f));
            }
            *(uint4*)(g_Bh + (size_t)row * KP2 + (256 + tt) * 8) = t.u;
        }
        return;
    }

    if (bb >= PREP_CTX) {
        const int r0 = (bb - PREP_CTX) * 2;
        #pragma unroll
        for (int rep = 0; rep < 2; rep++) {
            const int row = r0 + rep;
            H8 o;
            cvt8(o, x + (size_t)row * D_MODEL + tid * 8);
            *(uint4*)(g_Ah + (size_t)row * KP2 + tid * 8) = o.u;
        }
        if (tid < 16) {
            const int rep = tid >> 3, tt = tid & 7;
            const int row = r0 + rep;
            H8 t;
            #pragma unroll
            for (int i = 0; i < 4; i++) t.h2[i] = __float22half2_rn(make_float2(0.f, 0.f));
            *(uint4*)(g_Ah + (size_t)row * KP2 + (256 + tt) * 8) = t.u;
        }
        return;
    }

    // ---- fused ctx chain (unchanged) ----
    float* Ws  = (float*)buf;
    float* Xs  = (float*)(buf + 16384);
    float* As  = (float*)buf;
    float* Xs2 = (float*)(buf + 16512);
    float* cfs = (float*)(buf + 24960);
    float* ys  = (float*)(buf + 25472);

    const int tn = tid & 31;
    const int tm = tid >> 5;
    const int b0 = bb * 16;

    float acc[2][4];
    #pragma unroll
    for (int i = 0; i < 2; i++)
        #pragma unroll
        for (int j = 0; j < 4; j++) acc[i][j] = 0.f;

    for (int k0 = 0; k0 < D_MODEL; k0 += 32) {
        if (tid < 128) {
            int row = tid >> 3, c4 = tid & 7;
            *(float4*)&Xs[row * 36 + c4 * 4] =
                *(const float4*)(ctx + (size_t)(b0 + row) * D_MODEL + k0 + c4 * 4);
        }
        #pragma unroll
        for (int i = 0; i < 4; i++) {
            int idx = tid + i * 256;
            int j = idx >> 3, c4 = idx & 7;
            float4 v = *(const float4*)(cw + (size_t)j * D_MODEL + k0 + c4 * 4);
            Ws[(c4*4+0)*128 + j] = v.x;
            Ws[(c4*4+1)*128 + j] = v.y;
            Ws[(c4*4+2)*128 + j] = v.z;
            Ws[(c4*4+3)*128 + j] = v.w;
        }
        __syncthreads();
        #pragma unroll 8
        for (int kk = 0; kk < 32; kk++) {
            float x0 = Xs[(tm*2)*36 + kk], x1 = Xs[(tm*2+1)*36 + kk];
            float4 wv = *(const float4*)&Ws[kk*128 + tn*4];
            acc[0][0] += x0*wv.x; acc[0][1] += x0*wv.y;
            acc[0][2] += x0*wv.z; acc[0][3] += x0*wv.w;
            acc[1][0] += x1*wv.x; acc[1][1] += x1*wv.y;
            acc[1][2] += x1*wv.z; acc[1][3] += x1*wv.w;
        }
        __syncthreads();
    }
    {
        float4 cbv = *(const float4*)(cb + tn * 4);
        #pragma unroll
        for (int mi = 0; mi < 2; mi++) {
            acc[mi][0] += cbv.x; acc[mi][1] += cbv.y;
            acc[mi][2] += cbv.z; acc[mi][3] += cbv.w;
        }
    }

    float4 lgv = *(const float4*)(lg + tn * 4);
    float4 lbv = *(const float4*)(lb + tn * 4);
    #pragma unroll
    for (int mi = 0; mi < 2; mi++) {
        float s = acc[mi][0]+acc[mi][1]+acc[mi][2]+acc[mi][3];
        float s2 = acc[mi][0]*acc[mi][0]+acc[mi][1]*acc[mi][1]
                 + acc[mi][2]*acc[mi][2]+acc[mi][3]*acc[mi][3];
        #pragma unroll
        for (int o = 16; o > 0; o >>= 1) {
            s  += __shfl_xor_sync(0xffffffffu, s,  o);
            s2 += __shfl_xor_sync(0xffffffffu, s2, o);
        }
        float mu = s * (1.f/128.f);
        float var = s2 * (1.f/128.f) - mu*mu;
        float rstd = rsqrtf(var + LN_EPS);
        float g[4];
        const float* lgp = (const float*)&lgv;
        const float* lbp = (const float*)&lbv;
        #pragma unroll
        for (int ni = 0; ni < 4; ni++) {
            float hn = (acc[mi][ni] - mu) * rstd * lgp[ni] + lbp[ni];
            g[ni] = 0.5f * hn * (1.f + erff(hn * 0.70710678118654752f));
        }
        #pragma unroll
        for (int n = 0; n < NBASIS; n++) {
            float4 wv = *(const float4*)(cfw + n * HIDDEN + tn * 4);
            float p = g[0]*wv.x + g[1]*wv.y + g[2]*wv.z + g[3]*wv.w;
            #pragma unroll
            for (int o = 16; o > 0; o >>= 1) p += __shfl_xor_sync(0xffffffffu, p, o);
            if (tn == 0) cfs[(tm*2+mi)*8 + n] = p + cfb[n];
        }
    }
    __syncthreads();

    float y0 = 0.f, y1 = 0.f;
    for (int k0 = 0; k0 < D_MODEL; k0 += 128) {
        #pragma unroll
        for (int i = 0; i < 4; i++) {
            int idx = tid + i * 256;
            int j = idx >> 5, c4 = idx & 31;
            float4 v = *(const float4*)(A + (size_t)j * D_MODEL + k0 + c4 * 4);
            float* dst = &As[j * 129 + c4 * 4];
            dst[0] = v.x; dst[1] = v.y; dst[2] = v.z; dst[3] = v.w;
        }
        #pragma unroll
        for (int i = 0; i < 2; i++) {
            int idx = tid + i * 256;
            int r = idx >> 5, c4 = idx & 31;
            *(float4*)&Xs2[r * 132 + c4 * 4] =
                *(const float4*)(x + (size_t)(b0 + r) * D_MODEL + k0 + c4 * 4);
        }
        __syncthreads();
        const float* ar = As + tn * 129;
        const float* x0p = Xs2 + (tm*2) * 132;
        const float* x1p = Xs2 + (tm*2+1) * 132;
        #pragma unroll 16
        for (int kk = 0; kk < 128; kk++) {
            float a = ar[kk];
            y0 += a * x0p[kk];
            y1 += a * x1p[kk];
        }
        __syncthreads();
    }
    ys[(tm*2)*33 + tn]   = y0;
    ys[(tm*2+1)*33 + tn] = y1;
    __syncthreads();

    if (tid < 64) {
        int row = tid >> 2, r = tid & 3;
        float cfr[8], z = 0.f;
        #pragma unroll
        for (int n = 0; n < 8; n++) {
            cfr[n] = cfs[row*8 + n];
            z += cfr[n] * ys[row*33 + n*4 + r];
        }
        #pragma unroll
        for (int n = 0; n < 8; n++)
            g_Ah[(size_t)(b0 + row) * KP2 + D_MODEL + n*4 + r] = __float2half_rn(cfr[n] * z);
    }
}

// ============================================================================
// helpers
// ============================================================================
__device__ __forceinline__ uint32_t smem_u32(const void* p) {
    return (uint32_t)__cvta_generic_to_shared(p);
}
__device__ __forceinline__ void mbar_init(uint32_t a, uint32_t cnt) {
    asm volatile("mbarrier.init.shared.b64 [%0], %1;" :: "r"(a), "r"(cnt) : "memory");
}
__device__ __forceinline__ void mbar_expect_tx(uint32_t a, uint32_t bytes) {
    asm volatile("mbarrier.arrive.expect_tx.shared.b64 _, [%0], %1;" :: "r"(a), "r"(bytes) : "memory");
}
__device__ __forceinline__ void mbar_wait(uint32_t a, uint32_t parity) {
    asm volatile(
        "{\n\t.reg .pred P1;\n\t"
        "WL_%=:\n\t"
        "mbarrier.try_wait.parity.acquire.cta.shared::cta.b64 P1, [%0], %1, 0x989680;\n\t"
        "@P1 bra.uni WD_%=;\n\t"
        "bra.uni WL_%=;\n\t"
        "WD_%=:\n\t}" :: "r"(a), "r"(parity) : "memory");
}
__device__ __forceinline__ void mbar_wait_relaxed(uint32_t a, uint32_t parity) {
    asm volatile(
        "{\n\t.reg .pred P1;\n\t"
        "WL_%=:\n\t"
        "mbarrier.try_wait.parity.relaxed.cta.shared::cta.b64 P1, [%0], %1, 0x989680;\n\t"
        "@P1 bra.uni WD_%=;\n\t"
        "bra.uni WL_%=;\n\t"
        "WD_%=:\n\t}" :: "r"(a), "r"(parity) : "memory");
}
__device__ __forceinline__ uint32_t elect_one() {
    uint32_t pred;
    asm volatile("{\n\t.reg .pred p;\n\telect.sync _|p, 0xFFFFFFFF;\n\t"
                 "selp.b32 %0, 1, 0, p;\n\t}" : "=r"(pred));
    return pred;
}
__device__ __forceinline__ uint32_t ctarank() {
    uint32_t r; asm("mov.u32 %0, %%cluster_ctarank;" : "=r"(r)); return r;
}
__device__ __forceinline__ void mbar_arrive_leader(uint32_t a) {
    asm volatile(
        "{\n\t.reg .b32 la;\n\tand.b32 la, %0, 0xFEFFFFFF;\n\t"
        "mbarrier.arrive.shared::cluster.b64 _, [la];\n\t}"
        :: "r"(a) : "memory");
}

#define CP16(d, s)  asm volatile("cp.async.cg.shared.global [%0], [%1], 16;" :: "r"(d), "l"(s))
#define CP_COMMIT() asm volatile("cp.async.commit_group;")
#define CP_WAIT(n)  asm volatile("cp.async.wait_group %0;" :: "n"(n))
__device__ __forceinline__ void ldsm4(uint32_t& r0, uint32_t& r1, uint32_t& r2, uint32_t& r3, uint32_t a) {
    asm volatile("ldmatrix.sync.aligned.m8n8.x4.shared.b16 {%0,%1,%2,%3}, [%4];"
                 : "=r"(r0), "=r"(r1), "=r"(r2), "=r"(r3) : "r"(a));
}
__device__ __forceinline__ void mma16816(float* c, const uint32_t* a, const uint32_t* b) {
    asm volatile("mma.sync.aligned.m16n8k16.row.col.f32.f16.f16.f32 "
                 "{%0,%1,%2,%3}, {%4,%5,%6,%7}, {%8,%9}, {%0,%1,%2,%3};"
                 : "+f"(c[0]), "+f"(c[1]), "+f"(c[2]), "+f"(c[3])
                 : "r"(a[0]), "r"(a[1]), "r"(a[2]), "r"(a[3]), "r"(b[0]), "r"(b[1]));
}

// ============================================================================
// persistent main GEMM, half-tile pipelined:
// per tile, two N=256 halves with independent TMEM halves + barriers;
// MMA of half p overlaps epilogue of half 1-p.
// warps 0-7 epilogue, warp 8 producer (2 passes/tile), warp 9 consumer
// ============================================================================
__global__ void __launch_bounds__(320, 1) __cluster_dims__(2, 1, 1)
gemm_tc(const __grid_constant__ CUtensorMap tmA,
        const __grid_constant__ CUtensorMap tmB,
        const float* __restrict__ bias,
        float* __restrict__ out) {
    extern __shared__ char smem[];
#if HAS_TCGEN05
    const uint32_t sb = smem_u32(smem);
    const int tid = threadIdx.x;
    const int wid = tid >> 5;
    const int lane = tid & 31;
    const uint32_t rank = ctarank();
    const int cid = blockIdx.x >> 1;

    if (tid == 0) {
        #pragma unroll
        for (int s = 0; s < GSTAGES; s++) {
            mbar_init(sb + OFF_FULL  + s * 8, 1);
            mbar_init(sb + OFF_EMPTY + s * 8, 1);
        }
        mbar_init(sb + OFF_DONE0, 2);   // epi_done[half]: one arrive per CTA
        mbar_init(sb + OFF_DONE1, 2);
        mbar_init(sb + OFF_EPIF0, 1);   // epi_full[half]: multicast commit
        mbar_init(sb + OFF_EPIF1, 1);
    }
    if (wid == 9) {
        asm volatile("tcgen05.alloc.cta_group::2.sync.aligned.shared::cta.b32 [%0], %1;"
                     :: "r"(sb + OFF_TMEM), "r"(512u) : "memory");
    }
    __syncthreads();
    uint32_t tbase;
    asm volatile("ld.shared.b32 %0, [%1];" : "=r"(tbase) : "r"(sb + OFF_TMEM));

    asm volatile("barrier.cluster.arrive.aligned;" ::: "memory");
    asm volatile("barrier.cluster.wait.aligned;" ::: "memory");

    // ---- producer: warp 8 lane 0 in BOTH CTAs; 2 passes per tile ----
    if (tid == 256) {
        int pphase = 1, pstage = 0;
        for (int t = cid; t < NTILES; t += NCLUSTERS) {
            const int arow = (t & 7) * 256 + (int)rank * 128;
            const int n0   = (t >> 3) * GBN;
            #pragma unroll 1
            for (int p = 0; p < 2; p++) {
                const int brow = n0 + p * 256 + (int)rank * 128;
                for (int kt = 0; kt < KTILES; kt++) {
                    mbar_wait_relaxed(sb + OFF_EMPTY + pstage * 8, (uint32_t)pphase);
                    if (rank == 0) mbar_expect_tx(sb + OFF_FULL + pstage * 8, 2 * STAGE_BYTES);
                    const int k0 = kt * GBK;
                    const uint32_t st = sb + OFF_TILE + pstage * STAGE_BYTES;
                    const uint32_t fb = sb + OFF_FULL + pstage * 8;
                    asm volatile(
                        "{\n\t.reg .b32 lb;\n\tand.b32 lb, %5, 0xFEFFFFFF;\n\t"
                        "cp.async.bulk.tensor.3d.cta_group::2.shared::cluster.global"
                        ".tile.mbarrier::complete_tx::bytes [%0], [%1, {%2, %3, %4}], [lb];\n\t}"
                        :: "r"(st), "l"(&tmA), "r"(k0), "r"(arow), "r"(0), "r"(fb) : "memory");
                    asm volatile(
                        "{\n\t.reg .b32 lb;\n\tand.b32 lb, %5, 0xFEFFFFFF;\n\t"
                        "cp.async.bulk.tensor.3d.cta_group::2.shared::cluster.global"
                        ".tile.mbarrier::complete_tx::bytes [%0], [%1, {%2, %3, %4}], [lb];\n\t}"
                        :: "r"(st + 16384), "l"(&tmB), "r"(k0), "r"(brow), "r"(0), "r"(fb) : "memory");
                    if (++pstage == GSTAGES) { pstage = 0; pphase ^= 1; }
                }
            }
        }
    }

    // ---- consumer: warp 9, leader CTA; half-pipelined ----
    if (wid == 9 && rank == 0) {
        if (elect_one()) {
            int cphase = 0, cstage = 0, ti = 0;
            for (int t = cid; t < NTILES; t += NCLUSTERS, ti++) {
                #pragma unroll 1
                for (int p = 0; p < 2; p++) {
                    if (ti > 0) {   // previous tile's epilogue must free this TMEM half
                        mbar_wait(sb + (p ? OFF_DONE1 : OFF_DONE0), (uint32_t)((ti - 1) & 1));
                        asm volatile("tcgen05.fence::after_thread_sync;" ::: "memory");
                    }
                    const uint32_t dst = tbase + (uint32_t)(p * 256);
                    for (int kt = 0; kt < KTILES; kt++) {
                        mbar_wait(sb + OFF_FULL + cstage * 8, (uint32_t)cphase);
                        const uint32_t st = sb + OFF_TILE + cstage * STAGE_BYTES;
                        const uint64_t dbase = (uint64_t(2) << 61) | (uint64_t(1) << 46)
                                             | (uint64_t(64) << 32) | (uint64_t(1) << 16);
                        const uint64_t ad = dbase | ((uint64_t)(st >> 4) & 0x3FFF);
                        const uint64_t bd = dbase | ((uint64_t)((st + 16384) >> 4) & 0x3FFF);
                        #pragma unroll
                        for (int ks = 0; ks < 4; ks++) {
                            uint32_t en = (kt | ks) ? 1u : 0u;
                            asm volatile(
                                "{\n\t.reg .pred pp;\n\tsetp.ne.u32 pp, %5, 0;\n\t"
                                "tcgen05.mma.cta_group::2.kind::f16 [%0], %1, %2, %3, "
                                "{%4,%4,%4,%4,%4,%4,%4,%4}, pp;\n\t}"
                                :: "r"(dst), "l"(ad + ks*2), "l"(bd + ks*2), "r"(IDESC), "r"(0u), "r"(en) : "memory");
                        }
                        asm volatile(
                            "tcgen05.commit.cta_group::2.mbarrier::arrive::one.shared::cluster"
                            ".multicast::cluster.b64 [%0], %1;"
                            :: "r"(sb + OFF_EMPTY + cstage * 8), "h"((uint16_t)3) : "memory");
                        if (++cstage == GSTAGES) { cstage = 0; cphase ^= 1; }
                    }
                    asm volatile(
                        "tcgen05.commit.cta_group::2.mbarrier::arrive::one.shared::cluster"
                        ".multicast::cluster.b64 [%0], %1;"
                        :: "r"(sb + (p ? OFF_EPIF1 : OFF_EPIF0)), "h"((uint16_t)3) : "memory");
                }
            }
        }
    }

    // ---- epilogue: warps 0..7, both CTAs; per half: 4 col-blocks per warp ----
    if (wid < 8) {
        const int sub = wid & 3;        // TMEM subpartition (warp % 4)
        const int grp = wid >> 2;       // block group within the half
        float* tsm = (float*)(smem + OFF_EPI + wid * 4224);   // 32 x 33 fp32
        int ti = 0;
        for (int t = cid; t < NTILES; t += NCLUSTERS, ti++) {
            const int rowbase = (t & 7) * 256 + (int)rank * 128 + sub * 32;
            const int n0 = (t >> 3) * GBN;
            #pragma unroll 1
            for (int p = 0; p < 2; p++) {
                mbar_wait(sb + (p ? OFF_EPIF1 : OFF_EPIF0), (uint32_t)(ti & 1));
                asm volatile("tcgen05.fence::after_thread_sync;" ::: "memory");
                #pragma unroll 1
                for (int i = 0; i < 4; i++) {
                    const int blk = grp * 4 + i;
                    const int cbase = n0 + p * 256 + blk * 32;
                    if (cbase < NUM_CLASSES) {
                        uint32_t r[32];
                        asm volatile(
                            "tcgen05.ld.sync.aligned.32x32b.x32.b32 "
                            "{%0,%1,%2,%3,%4,%5,%6,%7,%8,%9,%10,%11,%12,%13,%14,%15,"
                            "%16,%17,%18,%19,%20,%21,%22,%23,%24,%25,%26,%27,%28,%29,%30,%31}, [%32];"
                            : "=r"(r[0]),"=r"(r[1]),"=r"(r[2]),"=r"(r[3]),"=r"(r[4]),"=r"(r[5]),
                              "=r"(r[6]),"=r"(r[7]),"=r"(r[8]),"=r"(r[9]),"=r"(r[10]),"=r"(r[11]),
                              "=r"(r[12]),"=r"(r[13]),"=r"(r[14]),"=r"(r[15]),"=r"(r[16]),"=r"(r[17]),
                              "=r"(r[18]),"=r"(r[19]),"=r"(r[20]),"=r"(r[21]),"=r"(r[22]),"=r"(r[23]),
                              "=r"(r[24]),"=r"(r[25]),"=r"(r[26]),"=r"(r[27]),"=r"(r[28]),"=r"(r[29]),
                              "=r"(r[30]),"=r"(r[31])
                            : "r"(tbase + p * 256 + blk * 32));
                        asm volatile("tcgen05.wait::ld.sync.aligned;" ::: "memory");
                        #pragma unroll
                        for (int j = 0; j < 32; j++) tsm[lane * 33 + j] = __uint_as_float(r[j]);
                        __syncwarp();
                        const int c = cbase + lane;
                        const bool ok = (c < NUM_CLASSES);
                        const float bv = ok ? __ldg(bias + c) : 0.f;
                        #pragma unroll 8
                        for (int rr = 0; rr < 32; rr++) {
                            float v = tsm[rr * 33 + lane] + bv;
                            if (ok) out[(size_t)(rowbase + rr) * NUM_CLASSES + c] = v;
                        }
                        __syncwarp();
                    }
                }
                // all 8 epi warps done with this half -> free its TMEM
                asm volatile("bar.sync 3, 256;" ::: "memory");
                if (tid == 0) mbar_arrive_leader(sb + (p ? OFF_DONE1 : OFF_DONE0));
            }
        }
    }

    __syncthreads();
    if (wid == 9) {
        asm volatile("tcgen05.relinquish_alloc_permit.cta_group::2.sync.aligned;");
        asm volatile("tcgen05.dealloc.cta_group::2.sync.aligned.b32 %0, %1;"
                     :: "r"(tbase), "r"(512u));
    }
    asm volatile("barrier.cluster.arrive.aligned;" ::: "memory");
    asm volatile("barrier.cluster.wait.aligned;" ::: "memory");

#else  // ================= mma.sync fallback (base sm_103 cubin) =============
    const int tid  = threadIdx.x;
    const int lane = tid & 31;
    const int wid  = tid >> 5;
    if (wid < 8) {
        const int wm   = wid & 3;
        const int wn   = wid >> 2;

        __half* As = (__half*)smem;
        __half* Bs = (__half*)smem + (size_t)FSTAGES * FBM * FPITCH;
        const uint32_t sA = smem_u32(As), sB = smem_u32(Bs);

        const int crow = tid >> 2, cch = tid & 3;
        const uint32_t dA = sA + (crow * FPITCH + cch * 8) * 2;
        const uint32_t dB = sB + (crow * FPITCH + cch * 8) * 2;

        const int aRow = wm*32 + (lane & 15);
        const int aCol = (lane >> 4) << 3;
        const int bRow = wn*64 + (lane & 7) + ((lane >> 4) << 3);
        const int bCol = ((lane >> 3) & 1) << 3;
        const uint32_t aBase = sA + (aRow * FPITCH + aCol) * 2;
        const uint32_t bBase = sB + (bRow * FPITCH + bCol) * 2;

        const int FT = 16 * (NPAD2 / 128);
        for (int t = blockIdx.x; t < FT; t += gridDim.x) {
            const int m0 = (t & 15) * FBM;
            const int n0 = (t >> 4) * 128;
            const __half* gA = g_Ah + (size_t)(m0 + crow) * KP2 + cch * 8;
            const __half* gB = g_Bh + (size_t)(n0 + crow) * KP2 + cch * 8;

            float acc[2][8][4];
            #pragma unroll
            for (int i = 0; i < 2; i++)
                #pragma unroll
                for (int j = 0; j < 8; j++)
                    #pragma unroll
                    for (int k = 0; k < 4; k++) acc[i][j][k] = 0.f;

            #pragma unroll
            for (int s = 0; s < FSTAGES - 1; s++) {
                int koff = s * FBK;
                CP16(dA + s*FSTB,                 gA + koff);
                CP16(dA + s*FSTB + 64*FPITCH*2,   gA + (size_t)64*KP2 + koff);
                CP16(dB + s*FSTB,                 gB + koff);
                CP16(dB + s*FSTB + 64*FPITCH*2,   gB + (size_t)64*KP2 + koff);
                CP_COMMIT();
            }

            #pragma unroll 1
            for (int kt = 0; kt < FKT; kt++) {
                CP_WAIT(FSTAGES - 2);
                asm volatile("bar.sync 1, 256;" ::: "memory");
                const int s = kt % FSTAGES;
                int pf = kt + FSTAGES - 1;
                if (pf < FKT) {
                    int ps = pf % FSTAGES;
                    int koff = pf * FBK;
                    CP16(dA + ps*FSTB,               gA + koff);
                    CP16(dA + ps*FSTB + 64*FPITCH*2, gA + (size_t)64*KP2 + koff);
                    CP16(dB + ps*FSTB,               gB + koff);
                    CP16(dB + ps*FSTB + 64*FPITCH*2, gB + (size_t)64*KP2 + koff);
                }
                CP_COMMIT();

                const uint32_t aS = aBase + s * FSTB;
                const uint32_t bS = bBase + s * FSTB;
                #pragma unroll
                for (int ks = 0; ks < 2; ks++) {
                    uint32_t a[2][4];
                    #pragma unroll
                    for (int mt = 0; mt < 2; mt++)
                        ldsm4(a[mt][0], a[mt][1], a[mt][2], a[mt][3],
                              aS + (mt*16*FPITCH + ks*16) * 2);
                    uint32_t b[8][2];
                    #pragma unroll
                    for (int p = 0; p < 4; p++) {
                        uint32_t r0, r1, r2, r3;
                        ldsm4(r0, r1, r2, r3, bS + (p*16*FPITCH + ks*16) * 2);
                        b[2*p][0] = r0; b[2*p][1] = r1;
                        b[2*p+1][0] = r2; b[2*p+1][1] = r3;
                    }
                    #pragma unroll
                    for (int mt = 0; mt < 2; mt++)
                        #pragma unroll
                        for (int nt = 0; nt < 8; nt++)
                            mma16816(acc[mt][nt], a[mt], b[nt]);
                }
            }
            CP_WAIT(0);
            asm volatile("bar.sync 1, 256;" ::: "memory");

            #pragma unroll
            for (int mt = 0; mt < 2; mt++) {
                const int r0 = m0 + wm*32 + mt*16 + (lane >> 2);
                #pragma unroll
                for (int nt = 0; nt < 8; nt++) {
                    const int c = n0 + wn*64 + nt*8 + ((lane & 3) << 1);
                    if (c < NUM_CLASSES) {
                        float bb = __ldg(bias + c);
                        out[(size_t)r0      * NUM_CLASSES + c] = acc[mt][nt][0] + bb;
                        out[(size_t)(r0+8)  * NUM_CLASSES + c] = acc[mt][nt][2] + bb;
                    }
                    if (c + 1 < NUM_CLASSES) {
                        float bb = __ldg(bias + c + 1);
                        out[(size_t)r0      * NUM_CLASSES + c + 1] = acc[mt][nt][1] + bb;
                        out[(size_t)(r0+8)  * NUM_CLASSES + c + 1] = acc[mt][nt][3] + bb;
                    }
                }
            }
            asm volatile("bar.sync 1, 256;" ::: "memory");
        }
    }
#endif
}

// ============================================================================
typedef CUresult (*PFN_tmap)(CUtensorMap*, CUtensorMapDataType, cuuint32_t, void*,
                             const cuuint64_t*, const cuuint64_t*, const cuuint32_t*,
                             const cuuint32_t*, CUtensorMapInterleave, CUtensorMapSwizzle,
                             CUtensorMapL2promotion, CUtensorMapFloatOOBfill);

extern "C" void kernel_launch(void* const* d_in, const int* in_sizes, int n_in,
                              void* d_out, int out_size) {
    const float* x       = (const float*)d_in[0];
    const float* context = (const float*)d_in[1];
    const float* base_w  = (const float*)d_in[2];
    const float* base_b  = (const float*)d_in[3];
    const float* ctx_w   = (const float*)d_in[4];
    const float* ctx_b   = (const float*)d_in[5];
    const float* ln_g    = (const float*)d_in[6];
    const float* ln_b    = (const float*)d_in[7];
    const float* coeff_w = (const float*)d_in[8];
    const float* coeff_b = (const float*)d_in[9];
    const float* basis_A = (const float*)d_in[10];
    const float* basis_B = (const float*)d_in[11];
    float* out = (float*)d_out;
    (void)in_sizes; (void)n_in; (void)out_size;

    PFN_tmap encode = nullptr;
    cudaDriverEntryPointQueryResult qres;
    cudaGetDriverEntryPoint("cuTensorMapEncodeTiled", (void**)&encode,
                            cudaEnableDefault, &qres);

    void *pA = nullptr, *pB = nullptr;
    cudaGetSymbolAddress(&pA, g_Ah);
    cudaGetSymbolAddress(&pB, g_Bh);

    CUtensorMap tmA, tmB;
    if (encode) {
        cuuint64_t dimsA[3]    = {KP2, NB, 1};
        cuuint64_t stridesA[2] = {(cuuint64_t)KP2 * 2, (cuuint64_t)KP2 * 2 * NB};
        cuuint32_t box[3]      = {GBK, 128, 1};
        cuuint32_t es[3]       = {1, 1, 1};
        encode(&tmA, CU_TENSOR_MAP_DATA_TYPE_FLOAT16, 3, pA, dimsA, stridesA, box, es,
               CU_TENSOR_MAP_INTERLEAVE_NONE, CU_TENSOR_MAP_SWIZZLE_128B,
               CU_TENSOR_MAP_L2_PROMOTION_L2_128B, CU_TENSOR_MAP_FLOAT_OOB_FILL_NONE);
        cuuint64_t dimsB[3]    = {KP2, NPAD2, 1};
        cuuint64_t stridesB[2] = {(cuuint64_t)KP2 * 2, (cuuint64_t)KP2 * 2 * NPAD2};
        encode(&tmB, CU_TENSOR_MAP_DATA_TYPE_FLOAT16, 3, pB, dimsB, stridesB, box, es,
               CU_TENSOR_MAP_INTERLEAVE_NONE, CU_TENSOR_MAP_SWIZZLE_128B,
               CU_TENSOR_MAP_L2_PROMOTION_L2_128B, CU_TENSOR_MAP_FLOAT_OOB_FILL_NONE);
    }

    cudaFuncSetAttribute(gemm_tc, cudaFuncAttributeMaxDynamicSharedMemorySize, SMEM_TOTAL);

    prep<<<PREP_GRID, 256>>>(context, ctx_w, ctx_b, ln_g, ln_b,
                             coeff_w, coeff_b, x, basis_A, base_w, basis_B);

    gemm_tc<<<2 * NCLUSTERS, 320, SMEM_TOTAL>>>(tmA, tmB, base_b, out);
}